// round 2
// baseline (speedup 1.0000x reference)
#include <cuda_runtime.h>
#include <cuda_bf16.h>
#include <cstddef>

// Problem constants (fixed by the dataset)
#define M_NODES 100000
#define K_FIN   512
#define N_FOUT  256
#define N_EDGES 3200000

// ---------------------------------------------------------------------------
// Static device scratch (no allocations allowed anywhere)
// ---------------------------------------------------------------------------
__device__ float g_h[(size_t)M_NODES * N_FOUT];        // h = x @ W   (102.4 MB)
__device__ int   g_row_count[M_NODES];                 // per-row edge counts
__device__ int   g_row_start[M_NODES + 1];             // CSR row offsets
__device__ int   g_row_fill[M_NODES];                  // scatter cursors
__device__ int   g_csr_col[N_EDGES];                   // CSR column indices
__device__ float g_csr_val[N_EDGES];                   // CSR values

// ---------------------------------------------------------------------------
// Kernel 1: SGEMM  h[M,256] = x[M,512] @ W[512,256], fp32
// BM=128, BN=128, BK=16, 256 threads, 8x8 per thread
// ---------------------------------------------------------------------------
#define BM 128
#define BN 128
#define BK 16
#define TM 8
#define TN 8

__global__ __launch_bounds__(256, 2)
void sgemm_kernel(const float* __restrict__ A,   // [M, 512]
                  const float* __restrict__ B,   // [512, 256]
                  float* __restrict__ C)         // [M, 256]
{
    const int K = K_FIN;
    const int N = N_FOUT;
    const int M = M_NODES;

    __shared__ float As[BK][BM];   // transposed: [k][m]
    __shared__ float Bs[BK][BN];   // [k][n]

    const int bm = blockIdx.x * BM;
    const int bn = blockIdx.y * BN;
    const int tid = threadIdx.x;
    const int tx = tid & 15;       // 0..15 -> column group
    const int ty = tid >> 4;       // 0..15 -> row group

    float acc[TM][TN];
#pragma unroll
    for (int i = 0; i < TM; i++)
#pragma unroll
        for (int j = 0; j < TN; j++) acc[i][j] = 0.f;

    for (int k0 = 0; k0 < K; k0 += BK) {
        // --- load A tile: 128 rows x 16 k's = 512 float4, 2 per thread ---
#pragma unroll
        for (int i = 0; i < 2; i++) {
            int t   = tid + i * 256;
            int row = t >> 2;           // 0..127
            int k4  = (t & 3) * 4;      // 0,4,8,12
            int gm  = bm + row;
            float4 av;
            if (gm < M) {
                av = *reinterpret_cast<const float4*>(A + (size_t)gm * K + k0 + k4);
            } else {
                av = make_float4(0.f, 0.f, 0.f, 0.f);
            }
            As[k4 + 0][row] = av.x;
            As[k4 + 1][row] = av.y;
            As[k4 + 2][row] = av.z;
            As[k4 + 3][row] = av.w;
        }
        // --- load B tile: 16 rows x 128 cols = 512 float4, 2 per thread ---
#pragma unroll
        for (int i = 0; i < 2; i++) {
            int t   = tid + i * 256;
            int row = t >> 5;           // 0..15
            int c4  = (t & 31) * 4;     // 0..124
            float4 bv = *reinterpret_cast<const float4*>(
                B + (size_t)(k0 + row) * N + bn + c4);
            *reinterpret_cast<float4*>(&Bs[row][c4]) = bv;
        }
        __syncthreads();

#pragma unroll
        for (int kk = 0; kk < BK; kk++) {
            float ra[TM], rb[TN];
            *reinterpret_cast<float4*>(&ra[0]) =
                *reinterpret_cast<const float4*>(&As[kk][ty * TM + 0]);
            *reinterpret_cast<float4*>(&ra[4]) =
                *reinterpret_cast<const float4*>(&As[kk][ty * TM + 4]);
            *reinterpret_cast<float4*>(&rb[0]) =
                *reinterpret_cast<const float4*>(&Bs[kk][tx * TN + 0]);
            *reinterpret_cast<float4*>(&rb[4]) =
                *reinterpret_cast<const float4*>(&Bs[kk][tx * TN + 4]);
#pragma unroll
            for (int i = 0; i < TM; i++)
#pragma unroll
                for (int j = 0; j < TN; j++)
                    acc[i][j] += ra[i] * rb[j];
        }
        __syncthreads();
    }

    // --- store C ---
#pragma unroll
    for (int i = 0; i < TM; i++) {
        int gm = bm + ty * TM + i;
        if (gm < M) {
            float* crow = C + (size_t)gm * N + bn + tx * TN;
            *reinterpret_cast<float4*>(crow + 0) =
                make_float4(acc[i][0], acc[i][1], acc[i][2], acc[i][3]);
            *reinterpret_cast<float4*>(crow + 4) =
                make_float4(acc[i][4], acc[i][5], acc[i][6], acc[i][7]);
        }
    }
}

// ---------------------------------------------------------------------------
// CSR construction: count -> scan -> scatter
// ---------------------------------------------------------------------------
__global__ __launch_bounds__(256)
void count_kernel(const int* __restrict__ rows)
{
    int idx = blockIdx.x * blockDim.x + threadIdx.x;
    int stride = gridDim.x * blockDim.x;
    for (int e = idx; e < N_EDGES; e += stride) {
        atomicAdd(&g_row_count[rows[e]], 1);
    }
}

#define SCAN_T 1024
__global__ __launch_bounds__(SCAN_T)
void scan_kernel()
{
    __shared__ int part[SCAN_T];
    const int chunk = (M_NODES + SCAN_T - 1) / SCAN_T;   // 98
    int t = threadIdx.x;
    int begin = t * chunk;
    int end   = begin + chunk;
    if (end > M_NODES) end = M_NODES;
    if (begin > M_NODES) begin = M_NODES;

    int s = 0;
    for (int i = begin; i < end; i++) s += g_row_count[i];
    part[t] = s;
    __syncthreads();

    // Hillis-Steele inclusive scan over partials
    for (int off = 1; off < SCAN_T; off <<= 1) {
        int v = 0;
        if (t >= off) v = part[t - off];
        __syncthreads();
        part[t] += v;
        __syncthreads();
    }

    int run = (t == 0) ? 0 : part[t - 1];   // exclusive base for this chunk
    for (int i = begin; i < end; i++) {
        g_row_start[i] = run;
        run += g_row_count[i];
    }
    if (t == SCAN_T - 1) g_row_start[M_NODES] = run;  // == N_EDGES
}

__global__ __launch_bounds__(256)
void scatter_kernel(const int*   __restrict__ rows,
                    const int*   __restrict__ cols,
                    const float* __restrict__ vals)
{
    int idx = blockIdx.x * blockDim.x + threadIdx.x;
    int stride = gridDim.x * blockDim.x;
    for (int e = idx; e < N_EDGES; e += stride) {
        int r = rows[e];
        int pos = g_row_start[r] + atomicAdd(&g_row_fill[r], 1);
        g_csr_col[pos] = cols[e];
        g_csr_val[pos] = vals[e];
    }
}

// ---------------------------------------------------------------------------
// Kernel 2: CSR SpMM + fused ReLU.
// One warp per output row; each lane owns 8 consecutive floats (2 float4).
// out[r][:] = relu( sum_e csr_val[e] * h[csr_col[e]][:] )
// ---------------------------------------------------------------------------
__global__ __launch_bounds__(256)
void spmm_csr_kernel(const float* __restrict__ h,
                     float*       __restrict__ out)
{
    int warp_global = (blockIdx.x * blockDim.x + threadIdx.x) >> 5;
    int lane = threadIdx.x & 31;
    if (warp_global >= M_NODES) return;

    int row = warp_global;
    int s = g_row_start[row];
    int e = g_row_start[row + 1];

    float acc[8];
#pragma unroll
    for (int i = 0; i < 8; i++) acc[i] = 0.f;

    // 2-way manual unroll for memory-level parallelism
    int i = s;
    for (; i + 2 <= e; i += 2) {
        int   c0 = g_csr_col[i];
        float v0 = g_csr_val[i];
        int   c1 = g_csr_col[i + 1];
        float v1 = g_csr_val[i + 1];
        const float4* h0 = reinterpret_cast<const float4*>(h + (size_t)c0 * N_FOUT);
        const float4* h1 = reinterpret_cast<const float4*>(h + (size_t)c1 * N_FOUT);
        float4 a0 = __ldg(&h0[lane * 2 + 0]);
        float4 b0 = __ldg(&h0[lane * 2 + 1]);
        float4 a1 = __ldg(&h1[lane * 2 + 0]);
        float4 b1 = __ldg(&h1[lane * 2 + 1]);
        acc[0] += v0 * a0.x; acc[1] += v0 * a0.y; acc[2] += v0 * a0.z; acc[3] += v0 * a0.w;
        acc[4] += v0 * b0.x; acc[5] += v0 * b0.y; acc[6] += v0 * b0.z; acc[7] += v0 * b0.w;
        acc[0] += v1 * a1.x; acc[1] += v1 * a1.y; acc[2] += v1 * a1.z; acc[3] += v1 * a1.w;
        acc[4] += v1 * b1.x; acc[5] += v1 * b1.y; acc[6] += v1 * b1.z; acc[7] += v1 * b1.w;
    }
    for (; i < e; i++) {
        int   c = g_csr_col[i];
        float v = g_csr_val[i];
        const float4* hr = reinterpret_cast<const float4*>(h + (size_t)c * N_FOUT);
        float4 a = __ldg(&hr[lane * 2 + 0]);
        float4 b = __ldg(&hr[lane * 2 + 1]);
        acc[0] += v * a.x; acc[1] += v * a.y; acc[2] += v * a.z; acc[3] += v * a.w;
        acc[4] += v * b.x; acc[5] += v * b.y; acc[6] += v * b.z; acc[7] += v * b.w;
    }

    // fused ReLU + single store (output written exactly once -> no memset)
    float* orow = out + (size_t)row * N_FOUT + lane * 8;
    float4 o0 = make_float4(fmaxf(acc[0], 0.f), fmaxf(acc[1], 0.f),
                            fmaxf(acc[2], 0.f), fmaxf(acc[3], 0.f));
    float4 o1 = make_float4(fmaxf(acc[4], 0.f), fmaxf(acc[5], 0.f),
                            fmaxf(acc[6], 0.f), fmaxf(acc[7], 0.f));
    *reinterpret_cast<float4*>(orow + 0) = o0;
    *reinterpret_cast<float4*>(orow + 4) = o1;
}

// ---------------------------------------------------------------------------
// Launch
// ---------------------------------------------------------------------------
extern "C" void kernel_launch(void* const* d_in, const int* in_sizes, int n_in,
                              void* d_out, int out_size)
{
    const float* x        = (const float*)d_in[0];
    const int*   adj_rows = (const int*)  d_in[1];
    const int*   adj_cols = (const int*)  d_in[2];
    const float* adj_vals = (const float*)d_in[3];
    const float* weight   = (const float*)d_in[4];
    float*       out      = (float*)d_out;

    float* h = nullptr;
    int*   row_count = nullptr;
    int*   row_fill  = nullptr;
    cudaGetSymbolAddress((void**)&h, g_h);
    cudaGetSymbolAddress((void**)&row_count, g_row_count);
    cudaGetSymbolAddress((void**)&row_fill, g_row_fill);

    // Phase 0: zero CSR counters (async, capture-safe)
    cudaMemsetAsync(row_count, 0, M_NODES * sizeof(int), 0);
    cudaMemsetAsync(row_fill,  0, M_NODES * sizeof(int), 0);

    // Phase 1: h = x @ W  (independent of CSR build; same stream is fine)
    dim3 ggrid((M_NODES + BM - 1) / BM, N_FOUT / BN);
    sgemm_kernel<<<ggrid, 256>>>(x, weight, h);

    // Phase 2: CSR build
    count_kernel<<<1024, 256>>>(adj_rows);
    scan_kernel<<<1, SCAN_T>>>();
    scatter_kernel<<<1024, 256>>>(adj_rows, adj_cols, adj_vals);

    // Phase 3: CSR SpMM + fused ReLU (one warp per row)
    int nblocks = (M_NODES * 32 + 255) / 256;
    spmm_csr_kernel<<<nblocks, 256>>>(h, out);
}

// round 3
// speedup vs baseline: 1.6241x; 1.6241x over previous
#include <cuda_runtime.h>
#include <cuda_bf16.h>
#include <cstddef>
#include <cstdint>

// Problem constants (fixed by the dataset)
#define M_NODES 100000
#define K_FIN   512
#define N_FOUT  256
#define N_EDGES 3200000

// ---------------------------------------------------------------------------
// Static device scratch (no allocations allowed anywhere)
// ---------------------------------------------------------------------------
__device__ float g_h[(size_t)M_NODES * N_FOUT];        // h = x @ W   (102.4 MB)
__device__ int   g_row_count[M_NODES];                 // per-row edge counts
__device__ int   g_row_start[M_NODES + 1];             // CSR row offsets
__device__ int   g_row_fill[M_NODES];                  // scatter cursors
__device__ int   g_csr_col[N_EDGES];                   // CSR column indices
__device__ float g_csr_val[N_EDGES];                   // CSR values

// ---------------------------------------------------------------------------
// TF32 helpers
// ---------------------------------------------------------------------------
__device__ __forceinline__ uint32_t f2tf32(float f) {
    uint32_t u;
    asm("cvt.rna.tf32.f32 %0, %1;" : "=r"(u) : "f"(f));
    return u;
}

__device__ __forceinline__ void mma_tf32(float* c, const uint32_t* a,
                                         uint32_t b0, uint32_t b1) {
    asm volatile(
        "mma.sync.aligned.m16n8k8.row.col.f32.tf32.tf32.f32 "
        "{%0,%1,%2,%3}, {%4,%5,%6,%7}, {%8,%9}, {%0,%1,%2,%3};\n"
        : "+f"(c[0]), "+f"(c[1]), "+f"(c[2]), "+f"(c[3])
        : "r"(a[0]), "r"(a[1]), "r"(a[2]), "r"(a[3]), "r"(b0), "r"(b1));
}

// ---------------------------------------------------------------------------
// Kernel 1: TF32 tensor-core GEMM  h[M,256] = x[M,512] @ W[512,256]
// BM=128, BN=128, BK=32; 256 threads = 8 warps (4 along m x 2 along n),
// warp tile 32x64, mma m16n8k8.
// A smem: [kgroup][m][kslot]  — STS.128 conflict-free; fragment loads 2-way.
// B smem: [k][n+pad8]         — STS.128 conflict-free; fragment loads conflict-free.
// tf32 conversion done once at staging.
// ---------------------------------------------------------------------------
__global__ __launch_bounds__(256, 2)
void tf32_gemm_kernel(const float* __restrict__ A,   // [M, 512]
                      const float* __restrict__ W,   // [512, 256]
                      float* __restrict__ C)         // [M, 256]
{
    __shared__ __align__(16) uint32_t As[4][128][8];   // 16 KB
    __shared__ __align__(16) uint32_t Bs[32][136];     // 17 KB (pad 8)

    const int tid  = threadIdx.x;
    const int lane = tid & 31;
    const int warp = tid >> 5;
    const int gid  = lane >> 2;     // 0..7
    const int tig  = lane & 3;      // 0..3
    const int wm   = (warp & 3) * 32;
    const int wn   = (warp >> 2) * 64;
    const int bm   = blockIdx.x * 128;
    const int bn   = blockIdx.y * 128;

    float acc[2][8][4];
#pragma unroll
    for (int mt = 0; mt < 2; mt++)
#pragma unroll
        for (int nt = 0; nt < 8; nt++)
#pragma unroll
            for (int i = 0; i < 4; i++) acc[mt][nt][i] = 0.f;

    for (int k0 = 0; k0 < K_FIN; k0 += 32) {
        // ---- stage A: 128 rows x 32 k = 1024 float4, 4 per thread ----
#pragma unroll
        for (int i = 0; i < 4; i++) {
            int t   = tid + i * 256;
            int row = t >> 3;            // 0..127
            int k4  = (t & 7) << 2;      // 0,4,...,28
            int gm  = bm + row;
            float4 av = make_float4(0.f, 0.f, 0.f, 0.f);
            if (gm < M_NODES)
                av = *reinterpret_cast<const float4*>(A + (size_t)gm * K_FIN + k0 + k4);
            uint4 u = make_uint4(f2tf32(av.x), f2tf32(av.y), f2tf32(av.z), f2tf32(av.w));
            *reinterpret_cast<uint4*>(&As[k4 >> 3][row][k4 & 7]) = u;
        }
        // ---- stage B: 32 k-rows x 128 n = 1024 float4, 4 per thread ----
#pragma unroll
        for (int i = 0; i < 4; i++) {
            int t  = tid + i * 256;
            int kr = t >> 5;             // 0..31
            int c4 = (t & 31) << 2;      // 0..124
            float4 bv = *reinterpret_cast<const float4*>(
                W + (size_t)(k0 + kr) * N_FOUT + bn + c4);
            uint4 u = make_uint4(f2tf32(bv.x), f2tf32(bv.y), f2tf32(bv.z), f2tf32(bv.w));
            *reinterpret_cast<uint4*>(&Bs[kr][c4]) = u;
        }
        __syncthreads();

#pragma unroll
        for (int g = 0; g < 4; g++) {
            uint32_t a[2][4];
#pragma unroll
            for (int mt = 0; mt < 2; mt++) {
                int r0 = wm + mt * 16 + gid;
                a[mt][0] = As[g][r0][tig];          // (r,     c)
                a[mt][1] = As[g][r0 + 8][tig];      // (r+8,   c)
                a[mt][2] = As[g][r0][tig + 4];      // (r,     c+4)
                a[mt][3] = As[g][r0 + 8][tig + 4];  // (r+8,   c+4)
            }
#pragma unroll
            for (int nt = 0; nt < 8; nt++) {
                int n = wn + nt * 8 + gid;
                uint32_t b0 = Bs[g * 8 + tig][n];       // (k,   n)
                uint32_t b1 = Bs[g * 8 + tig + 4][n];   // (k+4, n)
                mma_tf32(acc[0][nt], a[0], b0, b1);
                mma_tf32(acc[1][nt], a[1], b0, b1);
            }
        }
        __syncthreads();
    }

    // ---- epilogue: float2 stores (c0,c1 / c2,c3 are adjacent columns) ----
#pragma unroll
    for (int mt = 0; mt < 2; mt++) {
#pragma unroll
        for (int nt = 0; nt < 8; nt++) {
            int r0 = bm + wm + mt * 16 + gid;
            int cc = bn + wn + nt * 8 + 2 * tig;
            if (r0 < M_NODES)
                *reinterpret_cast<float2*>(&C[(size_t)r0 * N_FOUT + cc]) =
                    make_float2(acc[mt][nt][0], acc[mt][nt][1]);
            int r1 = r0 + 8;
            if (r1 < M_NODES)
                *reinterpret_cast<float2*>(&C[(size_t)r1 * N_FOUT + cc]) =
                    make_float2(acc[mt][nt][2], acc[mt][nt][3]);
        }
    }
}

// ---------------------------------------------------------------------------
// CSR construction: count -> scan -> scatter  (unchanged from R2)
// ---------------------------------------------------------------------------
__global__ __launch_bounds__(256)
void count_kernel(const int* __restrict__ rows)
{
    int idx = blockIdx.x * blockDim.x + threadIdx.x;
    int stride = gridDim.x * blockDim.x;
    for (int e = idx; e < N_EDGES; e += stride) {
        atomicAdd(&g_row_count[rows[e]], 1);
    }
}

#define SCAN_T 1024
__global__ __launch_bounds__(SCAN_T)
void scan_kernel()
{
    __shared__ int part[SCAN_T];
    const int chunk = (M_NODES + SCAN_T - 1) / SCAN_T;   // 98
    int t = threadIdx.x;
    int begin = t * chunk;
    int end   = begin + chunk;
    if (end > M_NODES) end = M_NODES;
    if (begin > M_NODES) begin = M_NODES;

    int s = 0;
    for (int i = begin; i < end; i++) s += g_row_count[i];
    part[t] = s;
    __syncthreads();

    for (int off = 1; off < SCAN_T; off <<= 1) {
        int v = 0;
        if (t >= off) v = part[t - off];
        __syncthreads();
        part[t] += v;
        __syncthreads();
    }

    int run = (t == 0) ? 0 : part[t - 1];
    for (int i = begin; i < end; i++) {
        g_row_start[i] = run;
        run += g_row_count[i];
    }
    if (t == SCAN_T - 1) g_row_start[M_NODES] = run;
}

__global__ __launch_bounds__(256)
void scatter_kernel(const int*   __restrict__ rows,
                    const int*   __restrict__ cols,
                    const float* __restrict__ vals)
{
    int idx = blockIdx.x * blockDim.x + threadIdx.x;
    int stride = gridDim.x * blockDim.x;
    for (int e = idx; e < N_EDGES; e += stride) {
        int r = rows[e];
        int pos = g_row_start[r] + atomicAdd(&g_row_fill[r], 1);
        g_csr_col[pos] = cols[e];
        g_csr_val[pos] = vals[e];
    }
}

// ---------------------------------------------------------------------------
// Kernel 2: CSR SpMM + fused ReLU (unchanged from R2)
// ---------------------------------------------------------------------------
__global__ __launch_bounds__(256)
void spmm_csr_kernel(const float* __restrict__ h,
                     float*       __restrict__ out)
{
    int warp_global = (blockIdx.x * blockDim.x + threadIdx.x) >> 5;
    int lane = threadIdx.x & 31;
    if (warp_global >= M_NODES) return;

    int row = warp_global;
    int s = g_row_start[row];
    int e = g_row_start[row + 1];

    float acc[8];
#pragma unroll
    for (int i = 0; i < 8; i++) acc[i] = 0.f;

    int i = s;
    for (; i + 2 <= e; i += 2) {
        int   c0 = g_csr_col[i];
        float v0 = g_csr_val[i];
        int   c1 = g_csr_col[i + 1];
        float v1 = g_csr_val[i + 1];
        const float4* h0 = reinterpret_cast<const float4*>(h + (size_t)c0 * N_FOUT);
        const float4* h1 = reinterpret_cast<const float4*>(h + (size_t)c1 * N_FOUT);
        float4 a0 = __ldg(&h0[lane * 2 + 0]);
        float4 b0 = __ldg(&h0[lane * 2 + 1]);
        float4 a1 = __ldg(&h1[lane * 2 + 0]);
        float4 b1 = __ldg(&h1[lane * 2 + 1]);
        acc[0] += v0 * a0.x; acc[1] += v0 * a0.y; acc[2] += v0 * a0.z; acc[3] += v0 * a0.w;
        acc[4] += v0 * b0.x; acc[5] += v0 * b0.y; acc[6] += v0 * b0.z; acc[7] += v0 * b0.w;
        acc[0] += v1 * a1.x; acc[1] += v1 * a1.y; acc[2] += v1 * a1.z; acc[3] += v1 * a1.w;
        acc[4] += v1 * b1.x; acc[5] += v1 * b1.y; acc[6] += v1 * b1.z; acc[7] += v1 * b1.w;
    }
    for (; i < e; i++) {
        int   c = g_csr_col[i];
        float v = g_csr_val[i];
        const float4* hr = reinterpret_cast<const float4*>(h + (size_t)c * N_FOUT);
        float4 a = __ldg(&hr[lane * 2 + 0]);
        float4 b = __ldg(&hr[lane * 2 + 1]);
        acc[0] += v * a.x; acc[1] += v * a.y; acc[2] += v * a.z; acc[3] += v * a.w;
        acc[4] += v * b.x; acc[5] += v * b.y; acc[6] += v * b.z; acc[7] += v * b.w;
    }

    float* orow = out + (size_t)row * N_FOUT + lane * 8;
    float4 o0 = make_float4(fmaxf(acc[0], 0.f), fmaxf(acc[1], 0.f),
                            fmaxf(acc[2], 0.f), fmaxf(acc[3], 0.f));
    float4 o1 = make_float4(fmaxf(acc[4], 0.f), fmaxf(acc[5], 0.f),
                            fmaxf(acc[6], 0.f), fmaxf(acc[7], 0.f));
    *reinterpret_cast<float4*>(orow + 0) = o0;
    *reinterpret_cast<float4*>(orow + 4) = o1;
}

// ---------------------------------------------------------------------------
// Launch
// ---------------------------------------------------------------------------
extern "C" void kernel_launch(void* const* d_in, const int* in_sizes, int n_in,
                              void* d_out, int out_size)
{
    const float* x        = (const float*)d_in[0];
    const int*   adj_rows = (const int*)  d_in[1];
    const int*   adj_cols = (const int*)  d_in[2];
    const float* adj_vals = (const float*)d_in[3];
    const float* weight   = (const float*)d_in[4];
    float*       out      = (float*)d_out;

    float* h = nullptr;
    int*   row_count = nullptr;
    int*   row_fill  = nullptr;
    cudaGetSymbolAddress((void**)&h, g_h);
    cudaGetSymbolAddress((void**)&row_count, g_row_count);
    cudaGetSymbolAddress((void**)&row_fill, g_row_fill);

    // Phase 0: zero CSR counters
    cudaMemsetAsync(row_count, 0, M_NODES * sizeof(int), 0);
    cudaMemsetAsync(row_fill,  0, M_NODES * sizeof(int), 0);

    // Phase 1: h = x @ W  (TF32 tensor cores)
    dim3 ggrid((M_NODES + 127) / 128, N_FOUT / 128);
    tf32_gemm_kernel<<<ggrid, 256>>>(x, weight, h);

    // Phase 2: CSR build
    count_kernel<<<1024, 256>>>(adj_rows);
    scan_kernel<<<1, SCAN_T>>>();
    scatter_kernel<<<1024, 256>>>(adj_rows, adj_cols, adj_vals);

    // Phase 3: CSR SpMM + fused ReLU (one warp per row)
    int nblocks = (M_NODES * 32 + 255) / 256;
    spmm_csr_kernel<<<nblocks, 256>>>(h, out);
}

// round 4
// speedup vs baseline: 1.6273x; 1.0020x over previous
#include <cuda_runtime.h>
#include <cuda_bf16.h>
#include <cstddef>
#include <cstdint>

// Problem constants (fixed by the dataset)
#define M_NODES 100000
#define K_FIN   512
#define N_FOUT  256
#define N_EDGES 3200000

// ---------------------------------------------------------------------------
// Static device scratch (no allocations allowed anywhere)
// ---------------------------------------------------------------------------
__device__ float g_h[(size_t)M_NODES * N_FOUT];        // h = x @ W   (102.4 MB)
__device__ int   g_row_count[M_NODES];                 // per-row edge counts
__device__ int   g_row_start[M_NODES + 1];             // CSR row offsets
__device__ int   g_row_fill[M_NODES];                  // scatter cursors
__device__ int   g_csr_col[N_EDGES];                   // CSR column indices
__device__ float g_csr_val[N_EDGES];                   // CSR values

// ---------------------------------------------------------------------------
// TF32 helpers
// ---------------------------------------------------------------------------
__device__ __forceinline__ uint32_t f2tf32(float f) {
    uint32_t u;
    asm("cvt.rna.tf32.f32 %0, %1;" : "=r"(u) : "f"(f));
    return u;
}

__device__ __forceinline__ void mma_tf32(float* c, const uint32_t* a,
                                         uint32_t b0, uint32_t b1) {
    asm volatile(
        "mma.sync.aligned.m16n8k8.row.col.f32.tf32.tf32.f32 "
        "{%0,%1,%2,%3}, {%4,%5,%6,%7}, {%8,%9}, {%0,%1,%2,%3};\n"
        : "+f"(c[0]), "+f"(c[1]), "+f"(c[2]), "+f"(c[3])
        : "r"(a[0]), "r"(a[1]), "r"(a[2]), "r"(a[3]), "r"(b0), "r"(b1));
}

// ---------------------------------------------------------------------------
// Kernel 1: TF32 tensor-core GEMM  h[M,256] = x[M,512] @ W[512,256]
// BM=128, BN=128, BK=32; 256 threads = 8 warps (4 along m x 2 along n),
// warp tile 32x64, mma m16n8k8.
// A smem: [kgroup][m][kslot]  — STS.128 conflict-free; fragment loads 2-way.
// B smem: [k][n+pad8]         — STS.128 conflict-free; fragment loads conflict-free.
// tf32 conversion done once at staging.
// ---------------------------------------------------------------------------
__global__ __launch_bounds__(256, 2)
void tf32_gemm_kernel(const float* __restrict__ A,   // [M, 512]
                      const float* __restrict__ W,   // [512, 256]
                      float* __restrict__ C)         // [M, 256]
{
    __shared__ __align__(16) uint32_t As[4][128][8];   // 16 KB
    __shared__ __align__(16) uint32_t Bs[32][136];     // 17 KB (pad 8)

    const int tid  = threadIdx.x;
    const int lane = tid & 31;
    const int warp = tid >> 5;
    const int gid  = lane >> 2;     // 0..7
    const int tig  = lane & 3;      // 0..3
    const int wm   = (warp & 3) * 32;
    const int wn   = (warp >> 2) * 64;
    const int bm   = blockIdx.x * 128;
    const int bn   = blockIdx.y * 128;

    float acc[2][8][4];
#pragma unroll
    for (int mt = 0; mt < 2; mt++)
#pragma unroll
        for (int nt = 0; nt < 8; nt++)
#pragma unroll
            for (int i = 0; i < 4; i++) acc[mt][nt][i] = 0.f;

    for (int k0 = 0; k0 < K_FIN; k0 += 32) {
        // ---- stage A: 128 rows x 32 k = 1024 float4, 4 per thread ----
#pragma unroll
        for (int i = 0; i < 4; i++) {
            int t   = tid + i * 256;
            int row = t >> 3;            // 0..127
            int k4  = (t & 7) << 2;      // 0,4,...,28
            int gm  = bm + row;
            float4 av = make_float4(0.f, 0.f, 0.f, 0.f);
            if (gm < M_NODES)
                av = *reinterpret_cast<const float4*>(A + (size_t)gm * K_FIN + k0 + k4);
            uint4 u = make_uint4(f2tf32(av.x), f2tf32(av.y), f2tf32(av.z), f2tf32(av.w));
            *reinterpret_cast<uint4*>(&As[k4 >> 3][row][k4 & 7]) = u;
        }
        // ---- stage B: 32 k-rows x 128 n = 1024 float4, 4 per thread ----
#pragma unroll
        for (int i = 0; i < 4; i++) {
            int t  = tid + i * 256;
            int kr = t >> 5;             // 0..31
            int c4 = (t & 31) << 2;      // 0..124
            float4 bv = *reinterpret_cast<const float4*>(
                W + (size_t)(k0 + kr) * N_FOUT + bn + c4);
            uint4 u = make_uint4(f2tf32(bv.x), f2tf32(bv.y), f2tf32(bv.z), f2tf32(bv.w));
            *reinterpret_cast<uint4*>(&Bs[kr][c4]) = u;
        }
        __syncthreads();

#pragma unroll
        for (int g = 0; g < 4; g++) {
            uint32_t a[2][4];
#pragma unroll
            for (int mt = 0; mt < 2; mt++) {
                int r0 = wm + mt * 16 + gid;
                a[mt][0] = As[g][r0][tig];          // (r,     c)
                a[mt][1] = As[g][r0 + 8][tig];      // (r+8,   c)
                a[mt][2] = As[g][r0][tig + 4];      // (r,     c+4)
                a[mt][3] = As[g][r0 + 8][tig + 4];  // (r+8,   c+4)
            }
#pragma unroll
            for (int nt = 0; nt < 8; nt++) {
                int n = wn + nt * 8 + gid;
                uint32_t b0 = Bs[g * 8 + tig][n];       // (k,   n)
                uint32_t b1 = Bs[g * 8 + tig + 4][n];   // (k+4, n)
                mma_tf32(acc[0][nt], a[0], b0, b1);
                mma_tf32(acc[1][nt], a[1], b0, b1);
            }
        }
        __syncthreads();
    }

    // ---- epilogue: float2 stores (c0,c1 / c2,c3 are adjacent columns) ----
#pragma unroll
    for (int mt = 0; mt < 2; mt++) {
#pragma unroll
        for (int nt = 0; nt < 8; nt++) {
            int r0 = bm + wm + mt * 16 + gid;
            int cc = bn + wn + nt * 8 + 2 * tig;
            if (r0 < M_NODES)
                *reinterpret_cast<float2*>(&C[(size_t)r0 * N_FOUT + cc]) =
                    make_float2(acc[mt][nt][0], acc[mt][nt][1]);
            int r1 = r0 + 8;
            if (r1 < M_NODES)
                *reinterpret_cast<float2*>(&C[(size_t)r1 * N_FOUT + cc]) =
                    make_float2(acc[mt][nt][2], acc[mt][nt][3]);
        }
    }
}

// ---------------------------------------------------------------------------
// CSR construction: count -> scan -> scatter  (unchanged from R2)
// ---------------------------------------------------------------------------
__global__ __launch_bounds__(256)
void count_kernel(const int* __restrict__ rows)
{
    int idx = blockIdx.x * blockDim.x + threadIdx.x;
    int stride = gridDim.x * blockDim.x;
    for (int e = idx; e < N_EDGES; e += stride) {
        atomicAdd(&g_row_count[rows[e]], 1);
    }
}

#define SCAN_T 1024
__global__ __launch_bounds__(SCAN_T)
void scan_kernel()
{
    __shared__ int part[SCAN_T];
    const int chunk = (M_NODES + SCAN_T - 1) / SCAN_T;   // 98
    int t = threadIdx.x;
    int begin = t * chunk;
    int end   = begin + chunk;
    if (end > M_NODES) end = M_NODES;
    if (begin > M_NODES) begin = M_NODES;

    int s = 0;
    for (int i = begin; i < end; i++) s += g_row_count[i];
    part[t] = s;
    __syncthreads();

    for (int off = 1; off < SCAN_T; off <<= 1) {
        int v = 0;
        if (t >= off) v = part[t - off];
        __syncthreads();
        part[t] += v;
        __syncthreads();
    }

    int run = (t == 0) ? 0 : part[t - 1];
    for (int i = begin; i < end; i++) {
        g_row_start[i] = run;
        run += g_row_count[i];
    }
    if (t == SCAN_T - 1) g_row_start[M_NODES] = run;
}

__global__ __launch_bounds__(256)
void scatter_kernel(const int*   __restrict__ rows,
                    const int*   __restrict__ cols,
                    const float* __restrict__ vals)
{
    int idx = blockIdx.x * blockDim.x + threadIdx.x;
    int stride = gridDim.x * blockDim.x;
    for (int e = idx; e < N_EDGES; e += stride) {
        int r = rows[e];
        int pos = g_row_start[r] + atomicAdd(&g_row_fill[r], 1);
        g_csr_col[pos] = cols[e];
        g_csr_val[pos] = vals[e];
    }
}

// ---------------------------------------------------------------------------
// Kernel 2: CSR SpMM + fused ReLU (unchanged from R2)
// ---------------------------------------------------------------------------
__global__ __launch_bounds__(256)
void spmm_csr_kernel(const float* __restrict__ h,
                     float*       __restrict__ out)
{
    int warp_global = (blockIdx.x * blockDim.x + threadIdx.x) >> 5;
    int lane = threadIdx.x & 31;
    if (warp_global >= M_NODES) return;

    int row = warp_global;
    int s = g_row_start[row];
    int e = g_row_start[row + 1];

    float acc[8];
#pragma unroll
    for (int i = 0; i < 8; i++) acc[i] = 0.f;

    int i = s;
    for (; i + 2 <= e; i += 2) {
        int   c0 = g_csr_col[i];
        float v0 = g_csr_val[i];
        int   c1 = g_csr_col[i + 1];
        float v1 = g_csr_val[i + 1];
        const float4* h0 = reinterpret_cast<const float4*>(h + (size_t)c0 * N_FOUT);
        const float4* h1 = reinterpret_cast<const float4*>(h + (size_t)c1 * N_FOUT);
        float4 a0 = __ldg(&h0[lane * 2 + 0]);
        float4 b0 = __ldg(&h0[lane * 2 + 1]);
        float4 a1 = __ldg(&h1[lane * 2 + 0]);
        float4 b1 = __ldg(&h1[lane * 2 + 1]);
        acc[0] += v0 * a0.x; acc[1] += v0 * a0.y; acc[2] += v0 * a0.z; acc[3] += v0 * a0.w;
        acc[4] += v0 * b0.x; acc[5] += v0 * b0.y; acc[6] += v0 * b0.z; acc[7] += v0 * b0.w;
        acc[0] += v1 * a1.x; acc[1] += v1 * a1.y; acc[2] += v1 * a1.z; acc[3] += v1 * a1.w;
        acc[4] += v1 * b1.x; acc[5] += v1 * b1.y; acc[6] += v1 * b1.z; acc[7] += v1 * b1.w;
    }
    for (; i < e; i++) {
        int   c = g_csr_col[i];
        float v = g_csr_val[i];
        const float4* hr = reinterpret_cast<const float4*>(h + (size_t)c * N_FOUT);
        float4 a = __ldg(&hr[lane * 2 + 0]);
        float4 b = __ldg(&hr[lane * 2 + 1]);
        acc[0] += v * a.x; acc[1] += v * a.y; acc[2] += v * a.z; acc[3] += v * a.w;
        acc[4] += v * b.x; acc[5] += v * b.y; acc[6] += v * b.z; acc[7] += v * b.w;
    }

    float* orow = out + (size_t)row * N_FOUT + lane * 8;
    float4 o0 = make_float4(fmaxf(acc[0], 0.f), fmaxf(acc[1], 0.f),
                            fmaxf(acc[2], 0.f), fmaxf(acc[3], 0.f));
    float4 o1 = make_float4(fmaxf(acc[4], 0.f), fmaxf(acc[5], 0.f),
                            fmaxf(acc[6], 0.f), fmaxf(acc[7], 0.f));
    *reinterpret_cast<float4*>(orow + 0) = o0;
    *reinterpret_cast<float4*>(orow + 4) = o1;
}

// ---------------------------------------------------------------------------
// Launch
// ---------------------------------------------------------------------------
extern "C" void kernel_launch(void* const* d_in, const int* in_sizes, int n_in,
                              void* d_out, int out_size)
{
    const float* x        = (const float*)d_in[0];
    const int*   adj_rows = (const int*)  d_in[1];
    const int*   adj_cols = (const int*)  d_in[2];
    const float* adj_vals = (const float*)d_in[3];
    const float* weight   = (const float*)d_in[4];
    float*       out      = (float*)d_out;

    float* h = nullptr;
    int*   row_count = nullptr;
    int*   row_fill  = nullptr;
    cudaGetSymbolAddress((void**)&h, g_h);
    cudaGetSymbolAddress((void**)&row_count, g_row_count);
    cudaGetSymbolAddress((void**)&row_fill, g_row_fill);

    // Phase 0: zero CSR counters
    cudaMemsetAsync(row_count, 0, M_NODES * sizeof(int), 0);
    cudaMemsetAsync(row_fill,  0, M_NODES * sizeof(int), 0);

    // Phase 1: h = x @ W  (TF32 tensor cores)
    dim3 ggrid((M_NODES + 127) / 128, N_FOUT / 128);
    tf32_gemm_kernel<<<ggrid, 256>>>(x, weight, h);

    // Phase 2: CSR build
    count_kernel<<<1024, 256>>>(adj_rows);
    scan_kernel<<<1, SCAN_T>>>();
    scatter_kernel<<<1024, 256>>>(adj_rows, adj_cols, adj_vals);

    // Phase 3: CSR SpMM + fused ReLU (one warp per row)
    int nblocks = (M_NODES * 32 + 255) / 256;
    spmm_csr_kernel<<<nblocks, 256>>>(h, out);
}

// round 6
// speedup vs baseline: 1.7016x; 1.0457x over previous
#include <cuda_runtime.h>
#include <cuda_bf16.h>
#include <cstddef>
#include <cstdint>

// Problem constants (fixed by the dataset)
#define M_NODES 100000
#define K_FIN   512
#define N_FOUT  256
#define N_EDGES 3200000

// ---------------------------------------------------------------------------
// Static device scratch (no allocations allowed anywhere)
// ---------------------------------------------------------------------------
__device__ float g_h[(size_t)M_NODES * N_FOUT];        // h = x @ W   (102.4 MB)
__device__ int   g_row_count[M_NODES];                 // per-row edge counts
__device__ int   g_row_start[M_NODES + 1];             // CSR row offsets
__device__ int   g_row_fill[M_NODES];                  // scatter cursors
__device__ int   g_csr_col[N_EDGES];                   // CSR column indices
__device__ float g_csr_val[N_EDGES];                   // CSR values

// ---------------------------------------------------------------------------
// TF32 helpers
// ---------------------------------------------------------------------------
__device__ __forceinline__ uint32_t f2tf32(float f) {
    uint32_t u;
    asm("cvt.rna.tf32.f32 %0, %1;" : "=r"(u) : "f"(f));
    return u;
}

__device__ __forceinline__ void mma_tf32(float* c, const uint32_t* a,
                                         uint32_t b0, uint32_t b1) {
    asm volatile(
        "mma.sync.aligned.m16n8k8.row.col.f32.tf32.tf32.f32 "
        "{%0,%1,%2,%3}, {%4,%5,%6,%7}, {%8,%9}, {%0,%1,%2,%3};\n"
        : "+f"(c[0]), "+f"(c[1]), "+f"(c[2]), "+f"(c[3])
        : "r"(a[0]), "r"(a[1]), "r"(a[2]), "r"(a[3]), "r"(b0), "r"(b1));
}

// ---------------------------------------------------------------------------
// Kernel 1: TF32 tensor-core GEMM  h[M,256] = x[M,512] @ W[512,256]
// BM=128, BN=128, BK=32; 256 threads = 8 warps (4 along m x 2 along n),
// warp tile 32x64, mma m16n8k8.  (unchanged from the 707us version)
// ---------------------------------------------------------------------------
__global__ __launch_bounds__(256, 2)
void tf32_gemm_kernel(const float* __restrict__ A,   // [M, 512]
                      const float* __restrict__ W,   // [512, 256]
                      float* __restrict__ C)         // [M, 256]
{
    __shared__ __align__(16) uint32_t As[4][128][8];   // 16 KB
    __shared__ __align__(16) uint32_t Bs[32][136];     // 17 KB (pad 8)

    const int tid  = threadIdx.x;
    const int lane = tid & 31;
    const int warp = tid >> 5;
    const int gid  = lane >> 2;     // 0..7
    const int tig  = lane & 3;      // 0..3
    const int wm   = (warp & 3) * 32;
    const int wn   = (warp >> 2) * 64;
    const int bm   = blockIdx.x * 128;
    const int bn   = blockIdx.y * 128;

    float acc[2][8][4];
#pragma unroll
    for (int mt = 0; mt < 2; mt++)
#pragma unroll
        for (int nt = 0; nt < 8; nt++)
#pragma unroll
            for (int i = 0; i < 4; i++) acc[mt][nt][i] = 0.f;

    for (int k0 = 0; k0 < K_FIN; k0 += 32) {
        // ---- stage A: 128 rows x 32 k = 1024 float4, 4 per thread ----
#pragma unroll
        for (int i = 0; i < 4; i++) {
            int t   = tid + i * 256;
            int row = t >> 3;            // 0..127
            int k4  = (t & 7) << 2;      // 0,4,...,28
            int gm  = bm + row;
            float4 av = make_float4(0.f, 0.f, 0.f, 0.f);
            if (gm < M_NODES)
                av = *reinterpret_cast<const float4*>(A + (size_t)gm * K_FIN + k0 + k4);
            uint4 u = make_uint4(f2tf32(av.x), f2tf32(av.y), f2tf32(av.z), f2tf32(av.w));
            *reinterpret_cast<uint4*>(&As[k4 >> 3][row][k4 & 7]) = u;
        }
        // ---- stage B: 32 k-rows x 128 n = 1024 float4, 4 per thread ----
#pragma unroll
        for (int i = 0; i < 4; i++) {
            int t  = tid + i * 256;
            int kr = t >> 5;             // 0..31
            int c4 = (t & 31) << 2;      // 0..124
            float4 bv = *reinterpret_cast<const float4*>(
                W + (size_t)(k0 + kr) * N_FOUT + bn + c4);
            uint4 u = make_uint4(f2tf32(bv.x), f2tf32(bv.y), f2tf32(bv.z), f2tf32(bv.w));
            *reinterpret_cast<uint4*>(&Bs[kr][c4]) = u;
        }
        __syncthreads();

#pragma unroll
        for (int g = 0; g < 4; g++) {
            uint32_t a[2][4];
#pragma unroll
            for (int mt = 0; mt < 2; mt++) {
                int r0 = wm + mt * 16 + gid;
                a[mt][0] = As[g][r0][tig];
                a[mt][1] = As[g][r0 + 8][tig];
                a[mt][2] = As[g][r0][tig + 4];
                a[mt][3] = As[g][r0 + 8][tig + 4];
            }
#pragma unroll
            for (int nt = 0; nt < 8; nt++) {
                int n = wn + nt * 8 + gid;
                uint32_t b0 = Bs[g * 8 + tig][n];
                uint32_t b1 = Bs[g * 8 + tig + 4][n];
                mma_tf32(acc[0][nt], a[0], b0, b1);
                mma_tf32(acc[1][nt], a[1], b0, b1);
            }
        }
        __syncthreads();
    }

    // ---- epilogue ----
#pragma unroll
    for (int mt = 0; mt < 2; mt++) {
#pragma unroll
        for (int nt = 0; nt < 8; nt++) {
            int r0 = bm + wm + mt * 16 + gid;
            int cc = bn + wn + nt * 8 + 2 * tig;
            if (r0 < M_NODES)
                *reinterpret_cast<float2*>(&C[(size_t)r0 * N_FOUT + cc]) =
                    make_float2(acc[mt][nt][0], acc[mt][nt][1]);
            int r1 = r0 + 8;
            if (r1 < M_NODES)
                *reinterpret_cast<float2*>(&C[(size_t)r1 * N_FOUT + cc]) =
                    make_float2(acc[mt][nt][2], acc[mt][nt][3]);
        }
    }
}

// ---------------------------------------------------------------------------
// CSR construction: count -> scan -> scatter
// ---------------------------------------------------------------------------
__global__ __launch_bounds__(256)
void count_kernel(const int* __restrict__ rows)
{
    int idx = blockIdx.x * blockDim.x + threadIdx.x;
    int stride = gridDim.x * blockDim.x;
    for (int e = idx; e < N_EDGES; e += stride) {
        atomicAdd(&g_row_count[rows[e]], 1);
    }
}

#define SCAN_T 1024
__global__ __launch_bounds__(SCAN_T)
void scan_kernel()
{
    __shared__ int part[SCAN_T];
    const int chunk = (M_NODES + SCAN_T - 1) / SCAN_T;   // 98
    int t = threadIdx.x;
    int begin = t * chunk;
    int end   = begin + chunk;
    if (end > M_NODES) end = M_NODES;
    if (begin > M_NODES) begin = M_NODES;

    int s = 0;
    for (int i = begin; i < end; i++) s += g_row_count[i];
    part[t] = s;
    __syncthreads();

    for (int off = 1; off < SCAN_T; off <<= 1) {
        int v = 0;
        if (t >= off) v = part[t - off];
        __syncthreads();
        part[t] += v;
        __syncthreads();
    }

    int run = (t == 0) ? 0 : part[t - 1];
    for (int i = begin; i < end; i++) {
        g_row_start[i] = run;
        run += g_row_count[i];
    }
    if (t == SCAN_T - 1) g_row_start[M_NODES] = run;
}

__global__ __launch_bounds__(256)
void scatter_kernel(const int*   __restrict__ rows,
                    const int*   __restrict__ cols,
                    const float* __restrict__ vals)
{
    int idx = blockIdx.x * blockDim.x + threadIdx.x;
    int stride = gridDim.x * blockDim.x;
    for (int e = idx; e < N_EDGES; e += stride) {
        int r = rows[e];
        int pos = g_row_start[r] + atomicAdd(&g_row_fill[r], 1);
        g_csr_col[pos] = cols[e];
        g_csr_val[pos] = vals[e];
    }
}

// ---------------------------------------------------------------------------
// Kernel 2: CSR SpMM + fused ReLU (one warp per row)
// ---------------------------------------------------------------------------
__global__ __launch_bounds__(256)
void spmm_csr_kernel(const float* __restrict__ h,
                     float*       __restrict__ out)
{
    int warp_global = (blockIdx.x * blockDim.x + threadIdx.x) >> 5;
    int lane = threadIdx.x & 31;
    if (warp_global >= M_NODES) return;

    int row = warp_global;
    int s = g_row_start[row];
    int e = g_row_start[row + 1];

    float acc[8];
#pragma unroll
    for (int i = 0; i < 8; i++) acc[i] = 0.f;

    int i = s;
    for (; i + 2 <= e; i += 2) {
        int   c0 = g_csr_col[i];
        float v0 = g_csr_val[i];
        int   c1 = g_csr_col[i + 1];
        float v1 = g_csr_val[i + 1];
        const float4* h0 = reinterpret_cast<const float4*>(h + (size_t)c0 * N_FOUT);
        const float4* h1 = reinterpret_cast<const float4*>(h + (size_t)c1 * N_FOUT);
        float4 a0 = __ldg(&h0[lane * 2 + 0]);
        float4 b0 = __ldg(&h0[lane * 2 + 1]);
        float4 a1 = __ldg(&h1[lane * 2 + 0]);
        float4 b1 = __ldg(&h1[lane * 2 + 1]);
        acc[0] += v0 * a0.x; acc[1] += v0 * a0.y; acc[2] += v0 * a0.z; acc[3] += v0 * a0.w;
        acc[4] += v0 * b0.x; acc[5] += v0 * b0.y; acc[6] += v0 * b0.z; acc[7] += v0 * b0.w;
        acc[0] += v1 * a1.x; acc[1] += v1 * a1.y; acc[2] += v1 * a1.z; acc[3] += v1 * a1.w;
        acc[4] += v1 * b1.x; acc[5] += v1 * b1.y; acc[6] += v1 * b1.z; acc[7] += v1 * b1.w;
    }
    for (; i < e; i++) {
        int   c = g_csr_col[i];
        float v = g_csr_val[i];
        const float4* hr = reinterpret_cast<const float4*>(h + (size_t)c * N_FOUT);
        float4 a = __ldg(&hr[lane * 2 + 0]);
        float4 b = __ldg(&hr[lane * 2 + 1]);
        acc[0] += v * a.x; acc[1] += v * a.y; acc[2] += v * a.z; acc[3] += v * a.w;
        acc[4] += v * b.x; acc[5] += v * b.y; acc[6] += v * b.z; acc[7] += v * b.w;
    }

    float* orow = out + (size_t)row * N_FOUT + lane * 8;
    float4 o0 = make_float4(fmaxf(acc[0], 0.f), fmaxf(acc[1], 0.f),
                            fmaxf(acc[2], 0.f), fmaxf(acc[3], 0.f));
    float4 o1 = make_float4(fmaxf(acc[4], 0.f), fmaxf(acc[5], 0.f),
                            fmaxf(acc[6], 0.f), fmaxf(acc[7], 0.f));
    *reinterpret_cast<float4*>(orow + 0) = o0;
    *reinterpret_cast<float4*>(orow + 4) = o1;
}

// ---------------------------------------------------------------------------
// Launch.
// GEMM and CSR build are independent; run them on forked streams so the
// captured graph executes them concurrently (tensor-bound || L2/atomic-bound).
// Fork/join via events is the documented capture-legal multi-stream pattern.
// Stream/event handles are host-side resources, cached across calls
// (identical work is enqueued on every call; output is unaffected).
// ---------------------------------------------------------------------------
extern "C" void kernel_launch(void* const* d_in, const int* in_sizes, int n_in,
                              void* d_out, int out_size)
{
    const float* x        = (const float*)d_in[0];
    const int*   adj_rows = (const int*)  d_in[1];
    const int*   adj_cols = (const int*)  d_in[2];
    const float* adj_vals = (const float*)d_in[3];
    const float* weight   = (const float*)d_in[4];
    float*       out      = (float*)d_out;

    float* h = nullptr;
    int*   row_count = nullptr;
    int*   row_fill  = nullptr;
    cudaGetSymbolAddress((void**)&h, g_h);
    cudaGetSymbolAddress((void**)&row_count, g_row_count);
    cudaGetSymbolAddress((void**)&row_fill, g_row_fill);

    static cudaStream_t s2 = nullptr;
    static cudaEvent_t ev_fork = nullptr, ev_join = nullptr;
    if (s2 == nullptr) {
        cudaStreamCreateWithFlags(&s2, cudaStreamNonBlocking);
        cudaEventCreateWithFlags(&ev_fork, cudaEventDisableTiming);
        cudaEventCreateWithFlags(&ev_join, cudaEventDisableTiming);
    }

    // ---- fork: branch B (CSR build) onto s2 ----
    cudaEventRecord(ev_fork, 0);
    cudaStreamWaitEvent(s2, ev_fork, 0);

    // Branch B on s2: CSR build pipeline
    cudaMemsetAsync(row_count, 0, M_NODES * sizeof(int), s2);
    cudaMemsetAsync(row_fill,  0, M_NODES * sizeof(int), s2);
    count_kernel<<<1024, 256, 0, s2>>>(adj_rows);
    scan_kernel<<<1, SCAN_T, 0, s2>>>();
    scatter_kernel<<<1024, 256, 0, s2>>>(adj_rows, adj_cols, adj_vals);
    cudaEventRecord(ev_join, s2);

    // Branch A on the main (capture) stream: h = x @ W (TF32 tensor cores)
    dim3 ggrid((M_NODES + 127) / 128, N_FOUT / 128);
    tf32_gemm_kernel<<<ggrid, 256>>>(x, weight, h);

    // ---- join, then SpMM (needs both h and CSR) ----
    cudaStreamWaitEvent(0, ev_join, 0);
    int nblocks = (M_NODES * 32 + 255) / 256;
    spmm_csr_kernel<<<nblocks, 256>>>(h, out);
}

// round 7
// speedup vs baseline: 2.1055x; 1.2374x over previous
#include <cuda_runtime.h>
#include <cuda_fp16.h>
#include <cuda_bf16.h>
#include <cstddef>
#include <cstdint>

// Problem constants (fixed by the dataset)
#define M_NODES 100000
#define K_FIN   512
#define N_FOUT  256
#define N_EDGES 3200000

// ---------------------------------------------------------------------------
// Static device scratch (no allocations allowed anywhere)
// ---------------------------------------------------------------------------
__device__ __half g_h[(size_t)M_NODES * N_FOUT];       // h = x @ W  (fp16, 51.2 MB)
__device__ int    g_row_count[M_NODES];                // per-row edge counts
__device__ int    g_row_start[M_NODES + 1];            // CSR row offsets
__device__ int    g_row_fill[M_NODES];                 // scatter cursors
__device__ int    g_csr_col[N_EDGES];                  // CSR column indices
__device__ float  g_csr_val[N_EDGES];                  // CSR values

// ---------------------------------------------------------------------------
// TF32 helpers
// ---------------------------------------------------------------------------
__device__ __forceinline__ uint32_t f2tf32(float f) {
    uint32_t u;
    asm("cvt.rna.tf32.f32 %0, %1;" : "=r"(u) : "f"(f));
    return u;
}

__device__ __forceinline__ void mma_tf32(float* c, const uint32_t* a,
                                         uint32_t b0, uint32_t b1) {
    asm volatile(
        "mma.sync.aligned.m16n8k8.row.col.f32.tf32.tf32.f32 "
        "{%0,%1,%2,%3}, {%4,%5,%6,%7}, {%8,%9}, {%0,%1,%2,%3};\n"
        : "+f"(c[0]), "+f"(c[1]), "+f"(c[2]), "+f"(c[3])
        : "r"(a[0]), "r"(a[1]), "r"(a[2]), "r"(a[3]), "r"(b0), "r"(b1));
}

// ---------------------------------------------------------------------------
// Kernel 1: TF32 tensor-core GEMM  h[M,256] = x[M,512] @ W[512,256]
// BM=128, BN=128, BK=32; 256 threads = 8 warps (4 along m x 2 along n),
// warp tile 32x64, mma m16n8k8.  Epilogue now stores fp16.
// ---------------------------------------------------------------------------
__global__ __launch_bounds__(256, 2)
void tf32_gemm_kernel(const float* __restrict__ A,   // [M, 512]
                      const float* __restrict__ W,   // [512, 256]
                      __half* __restrict__ C)        // [M, 256] fp16
{
    __shared__ __align__(16) uint32_t As[4][128][8];   // 16 KB
    __shared__ __align__(16) uint32_t Bs[32][136];     // 17 KB (pad 8)

    const int tid  = threadIdx.x;
    const int lane = tid & 31;
    const int warp = tid >> 5;
    const int gid  = lane >> 2;     // 0..7
    const int tig  = lane & 3;      // 0..3
    const int wm   = (warp & 3) * 32;
    const int wn   = (warp >> 2) * 64;
    const int bm   = blockIdx.x * 128;
    const int bn   = blockIdx.y * 128;

    float acc[2][8][4];
#pragma unroll
    for (int mt = 0; mt < 2; mt++)
#pragma unroll
        for (int nt = 0; nt < 8; nt++)
#pragma unroll
            for (int i = 0; i < 4; i++) acc[mt][nt][i] = 0.f;

    for (int k0 = 0; k0 < K_FIN; k0 += 32) {
        // ---- stage A: 128 rows x 32 k = 1024 float4, 4 per thread ----
#pragma unroll
        for (int i = 0; i < 4; i++) {
            int t   = tid + i * 256;
            int row = t >> 3;            // 0..127
            int k4  = (t & 7) << 2;      // 0,4,...,28
            int gm  = bm + row;
            float4 av = make_float4(0.f, 0.f, 0.f, 0.f);
            if (gm < M_NODES)
                av = *reinterpret_cast<const float4*>(A + (size_t)gm * K_FIN + k0 + k4);
            uint4 u = make_uint4(f2tf32(av.x), f2tf32(av.y), f2tf32(av.z), f2tf32(av.w));
            *reinterpret_cast<uint4*>(&As[k4 >> 3][row][k4 & 7]) = u;
        }
        // ---- stage B: 32 k-rows x 128 n = 1024 float4, 4 per thread ----
#pragma unroll
        for (int i = 0; i < 4; i++) {
            int t  = tid + i * 256;
            int kr = t >> 5;             // 0..31
            int c4 = (t & 31) << 2;      // 0..124
            float4 bv = *reinterpret_cast<const float4*>(
                W + (size_t)(k0 + kr) * N_FOUT + bn + c4);
            uint4 u = make_uint4(f2tf32(bv.x), f2tf32(bv.y), f2tf32(bv.z), f2tf32(bv.w));
            *reinterpret_cast<uint4*>(&Bs[kr][c4]) = u;
        }
        __syncthreads();

#pragma unroll
        for (int g = 0; g < 4; g++) {
            uint32_t a[2][4];
#pragma unroll
            for (int mt = 0; mt < 2; mt++) {
                int r0 = wm + mt * 16 + gid;
                a[mt][0] = As[g][r0][tig];
                a[mt][1] = As[g][r0 + 8][tig];
                a[mt][2] = As[g][r0][tig + 4];
                a[mt][3] = As[g][r0 + 8][tig + 4];
            }
#pragma unroll
            for (int nt = 0; nt < 8; nt++) {
                int n = wn + nt * 8 + gid;
                uint32_t b0 = Bs[g * 8 + tig][n];
                uint32_t b1 = Bs[g * 8 + tig + 4][n];
                mma_tf32(acc[0][nt], a[0], b0, b1);
                mma_tf32(acc[1][nt], a[1], b0, b1);
            }
        }
        __syncthreads();
    }

    // ---- epilogue: fp16 stores (adjacent column pairs -> __half2) ----
#pragma unroll
    for (int mt = 0; mt < 2; mt++) {
#pragma unroll
        for (int nt = 0; nt < 8; nt++) {
            int r0 = bm + wm + mt * 16 + gid;
            int cc = bn + wn + nt * 8 + 2 * tig;
            if (r0 < M_NODES)
                *reinterpret_cast<__half2*>(&C[(size_t)r0 * N_FOUT + cc]) =
                    __floats2half2_rn(acc[mt][nt][0], acc[mt][nt][1]);
            int r1 = r0 + 8;
            if (r1 < M_NODES)
                *reinterpret_cast<__half2*>(&C[(size_t)r1 * N_FOUT + cc]) =
                    __floats2half2_rn(acc[mt][nt][2], acc[mt][nt][3]);
        }
    }
}

// ---------------------------------------------------------------------------
// CSR construction: count -> scan -> scatter
// ---------------------------------------------------------------------------
__global__ __launch_bounds__(256)
void count_kernel(const int* __restrict__ rows)
{
    int idx = blockIdx.x * blockDim.x + threadIdx.x;
    int stride = gridDim.x * blockDim.x;
    for (int e = idx; e < N_EDGES; e += stride) {
        atomicAdd(&g_row_count[rows[e]], 1);
    }
}

#define SCAN_T 1024
__global__ __launch_bounds__(SCAN_T)
void scan_kernel()
{
    __shared__ int part[SCAN_T];
    const int chunk = (M_NODES + SCAN_T - 1) / SCAN_T;   // 98
    int t = threadIdx.x;
    int begin = t * chunk;
    int end   = begin + chunk;
    if (end > M_NODES) end = M_NODES;
    if (begin > M_NODES) begin = M_NODES;

    int s = 0;
    for (int i = begin; i < end; i++) s += g_row_count[i];
    part[t] = s;
    __syncthreads();

    for (int off = 1; off < SCAN_T; off <<= 1) {
        int v = 0;
        if (t >= off) v = part[t - off];
        __syncthreads();
        part[t] += v;
        __syncthreads();
    }

    int run = (t == 0) ? 0 : part[t - 1];
    for (int i = begin; i < end; i++) {
        g_row_start[i] = run;
        run += g_row_count[i];
    }
    if (t == SCAN_T - 1) g_row_start[M_NODES] = run;
}

__global__ __launch_bounds__(256)
void scatter_kernel(const int*   __restrict__ rows,
                    const int*   __restrict__ cols,
                    const float* __restrict__ vals)
{
    int idx = blockIdx.x * blockDim.x + threadIdx.x;
    int stride = gridDim.x * blockDim.x;
    for (int e = idx; e < N_EDGES; e += stride) {
        int r = rows[e];
        int pos = g_row_start[r] + atomicAdd(&g_row_fill[r], 1);
        g_csr_col[pos] = cols[e];
        g_csr_val[pos] = vals[e];
    }
}

// ---------------------------------------------------------------------------
// Kernel 2: CSR SpMM + fused ReLU (one warp per row), fp16 h.
// Each lane owns 8 consecutive outputs -> one LDG.128 (8 halves) per edge.
// ---------------------------------------------------------------------------
__global__ __launch_bounds__(256)
void spmm_csr_kernel(const __half* __restrict__ h,
                     float*        __restrict__ out)
{
    int warp_global = (blockIdx.x * blockDim.x + threadIdx.x) >> 5;
    int lane = threadIdx.x & 31;
    if (warp_global >= M_NODES) return;

    int row = warp_global;
    int s = g_row_start[row];
    int e = g_row_start[row + 1];

    float acc[8];
#pragma unroll
    for (int i = 0; i < 8; i++) acc[i] = 0.f;

    int i = s;
    for (; i + 2 <= e; i += 2) {
        int   c0 = g_csr_col[i];
        float v0 = g_csr_val[i];
        int   c1 = g_csr_col[i + 1];
        float v1 = g_csr_val[i + 1];
        uint4 p0 = __ldg(reinterpret_cast<const uint4*>(h + (size_t)c0 * N_FOUT) + lane);
        uint4 p1 = __ldg(reinterpret_cast<const uint4*>(h + (size_t)c1 * N_FOUT) + lane);
        {
            const __half2* q = reinterpret_cast<const __half2*>(&p0);
#pragma unroll
            for (int j = 0; j < 4; j++) {
                float2 f = __half22float2(q[j]);
                acc[2 * j + 0] += v0 * f.x;
                acc[2 * j + 1] += v0 * f.y;
            }
        }
        {
            const __half2* q = reinterpret_cast<const __half2*>(&p1);
#pragma unroll
            for (int j = 0; j < 4; j++) {
                float2 f = __half22float2(q[j]);
                acc[2 * j + 0] += v1 * f.x;
                acc[2 * j + 1] += v1 * f.y;
            }
        }
    }
    for (; i < e; i++) {
        int   c = g_csr_col[i];
        float v = g_csr_val[i];
        uint4 p = __ldg(reinterpret_cast<const uint4*>(h + (size_t)c * N_FOUT) + lane);
        const __half2* q = reinterpret_cast<const __half2*>(&p);
#pragma unroll
        for (int j = 0; j < 4; j++) {
            float2 f = __half22float2(q[j]);
            acc[2 * j + 0] += v * f.x;
            acc[2 * j + 1] += v * f.y;
        }
    }

    float* orow = out + (size_t)row * N_FOUT + lane * 8;
    float4 o0 = make_float4(fmaxf(acc[0], 0.f), fmaxf(acc[1], 0.f),
                            fmaxf(acc[2], 0.f), fmaxf(acc[3], 0.f));
    float4 o1 = make_float4(fmaxf(acc[4], 0.f), fmaxf(acc[5], 0.f),
                            fmaxf(acc[6], 0.f), fmaxf(acc[7], 0.f));
    *reinterpret_cast<float4*>(orow + 0) = o0;
    *reinterpret_cast<float4*>(orow + 4) = o1;
}

// ---------------------------------------------------------------------------
// Launch: fork GEMM || CSR build, join, SpMM.
// ---------------------------------------------------------------------------
extern "C" void kernel_launch(void* const* d_in, const int* in_sizes, int n_in,
                              void* d_out, int out_size)
{
    const float* x        = (const float*)d_in[0];
    const int*   adj_rows = (const int*)  d_in[1];
    const int*   adj_cols = (const int*)  d_in[2];
    const float* adj_vals = (const float*)d_in[3];
    const float* weight   = (const float*)d_in[4];
    float*       out      = (float*)d_out;

    __half* h = nullptr;
    int*    row_count = nullptr;
    int*    row_fill  = nullptr;
    cudaGetSymbolAddress((void**)&h, g_h);
    cudaGetSymbolAddress((void**)&row_count, g_row_count);
    cudaGetSymbolAddress((void**)&row_fill, g_row_fill);

    static cudaStream_t s2 = nullptr;
    static cudaEvent_t ev_fork = nullptr, ev_join = nullptr;
    if (s2 == nullptr) {
        cudaStreamCreateWithFlags(&s2, cudaStreamNonBlocking);
        cudaEventCreateWithFlags(&ev_fork, cudaEventDisableTiming);
        cudaEventCreateWithFlags(&ev_join, cudaEventDisableTiming);
    }

    // ---- fork: branch B (CSR build) onto s2 ----
    cudaEventRecord(ev_fork, 0);
    cudaStreamWaitEvent(s2, ev_fork, 0);

    cudaMemsetAsync(row_count, 0, M_NODES * sizeof(int), s2);
    cudaMemsetAsync(row_fill,  0, M_NODES * sizeof(int), s2);
    count_kernel<<<1024, 256, 0, s2>>>(adj_rows);
    scan_kernel<<<1, SCAN_T, 0, s2>>>();
    scatter_kernel<<<1024, 256, 0, s2>>>(adj_rows, adj_cols, adj_vals);
    cudaEventRecord(ev_join, s2);

    // Branch A on the main stream: h = x @ W (TF32 tensor cores, fp16 out)
    dim3 ggrid((M_NODES + 127) / 128, N_FOUT / 128);
    tf32_gemm_kernel<<<ggrid, 256>>>(x, weight, h);

    // ---- join, then SpMM ----
    cudaStreamWaitEvent(0, ev_join, 0);
    int nblocks = (M_NODES * 32 + 255) / 256;
    spmm_csr_kernel<<<nblocks, 256>>>(h, out);
}

// round 8
// speedup vs baseline: 2.2756x; 1.0808x over previous
#include <cuda_runtime.h>
#include <cuda_fp16.h>
#include <cuda_bf16.h>
#include <cstddef>
#include <cstdint>

// Problem constants (fixed by the dataset)
#define M_NODES 100000
#define K_FIN   512
#define N_FOUT  256
#define N_EDGES 3200000

// ---------------------------------------------------------------------------
// Static device scratch (no allocations allowed anywhere)
// ---------------------------------------------------------------------------
__device__ __half g_h[(size_t)M_NODES * N_FOUT];       // h = x @ W  (fp16, 51.2 MB)
__device__ int    g_row_count[M_NODES];                // per-row edge counts
__device__ int    g_row_start[M_NODES + 1];            // CSR row offsets
__device__ int    g_row_fill[M_NODES];                 // scatter cursors
__device__ int    g_csr_col[N_EDGES];                  // CSR column indices
__device__ float  g_csr_val[N_EDGES];                  // CSR values

// ---------------------------------------------------------------------------
// fp16 MMA + ldmatrix helpers
// ---------------------------------------------------------------------------
__device__ __forceinline__ void mma_f16(float* c, const uint32_t* a,
                                        uint32_t b0, uint32_t b1) {
    asm volatile(
        "mma.sync.aligned.m16n8k16.row.col.f32.f16.f16.f32 "
        "{%0,%1,%2,%3}, {%4,%5,%6,%7}, {%8,%9}, {%0,%1,%2,%3};\n"
        : "+f"(c[0]), "+f"(c[1]), "+f"(c[2]), "+f"(c[3])
        : "r"(a[0]), "r"(a[1]), "r"(a[2]), "r"(a[3]), "r"(b0), "r"(b1));
}

#define LDSM_X4(r0, r1, r2, r3, addr)                                        \
    asm volatile("ldmatrix.sync.aligned.m8n8.x4.shared.b16 {%0,%1,%2,%3},[%4];" \
                 : "=r"(r0), "=r"(r1), "=r"(r2), "=r"(r3) : "r"(addr))

#define LDSM_X4_T(r0, r1, r2, r3, addr)                                      \
    asm volatile("ldmatrix.sync.aligned.m8n8.x4.trans.shared.b16 {%0,%1,%2,%3},[%4];" \
                 : "=r"(r0), "=r"(r1), "=r"(r2), "=r"(r3) : "r"(addr))

// ---------------------------------------------------------------------------
// Kernel 1: fp16 HMMA GEMM  h[M,256] = x[M,512] @ W[512,256]  (fp32 accum)
// BM=128, BN=128, BK=32; 256 threads = 8 warps (4 m x 2 n), warp tile 32x64,
// mma m16n8k16, fragments via ldmatrix / ldmatrix.trans.
// A smem [128][40] halves (pad: 20 words/row -> LDSM phases tile all banks).
// B smem [32][136] halves ([k][n]; coalesced staging, transpose in LDSM).
// ---------------------------------------------------------------------------
__global__ __launch_bounds__(256, 2)
void hgemm_kernel(const float* __restrict__ A,   // [M, 512] f32
                  const float* __restrict__ W,   // [512, 256] f32
                  __half* __restrict__ C)        // [M, 256] fp16
{
    __shared__ __align__(16) __half As[128][40];    // 10.0 KB
    __shared__ __align__(16) __half Bs[32][136];    //  8.5 KB

    const int tid  = threadIdx.x;
    const int lane = tid & 31;
    const int warp = tid >> 5;
    const int gid  = lane >> 2;     // 0..7
    const int tig  = lane & 3;      // 0..3
    const int wm   = (warp & 3) * 32;
    const int wn   = (warp >> 2) * 64;
    const int bm   = blockIdx.x * 128;
    const int bn   = blockIdx.y * 128;

    // ldmatrix per-lane source row mapping (matrix idx = lane>>3)
    const int li   = lane >> 3;           // 0..3
    const int l7   = lane & 7;            // 0..7
    const int frow = ((li & 1) << 3) + l7;  // row offset within 16
    const int fcol = (li >> 1) << 3;        // col offset 0 or 8

    const uint32_t as_base = (uint32_t)__cvta_generic_to_shared(&As[0][0]);
    const uint32_t bs_base = (uint32_t)__cvta_generic_to_shared(&Bs[0][0]);

    float acc[2][8][4];
#pragma unroll
    for (int mt = 0; mt < 2; mt++)
#pragma unroll
        for (int nt = 0; nt < 8; nt++)
#pragma unroll
            for (int i = 0; i < 4; i++) acc[mt][nt][i] = 0.f;

    for (int k0 = 0; k0 < K_FIN; k0 += 32) {
        // ---- stage A: 128 rows x 32 k; f32 global -> f16 smem ----
#pragma unroll
        for (int i = 0; i < 4; i++) {
            int t   = tid + i * 256;
            int row = t >> 3;            // 0..127
            int k4  = (t & 7) << 2;      // 0,4,...,28
            int gm  = bm + row;
            float4 av = make_float4(0.f, 0.f, 0.f, 0.f);
            if (gm < M_NODES)
                av = *reinterpret_cast<const float4*>(A + (size_t)gm * K_FIN + k0 + k4);
            *reinterpret_cast<__half2*>(&As[row][k4 + 0]) = __floats2half2_rn(av.x, av.y);
            *reinterpret_cast<__half2*>(&As[row][k4 + 2]) = __floats2half2_rn(av.z, av.w);
        }
        // ---- stage B: 32 k-rows x 128 n; f32 global -> f16 smem [k][n] ----
#pragma unroll
        for (int i = 0; i < 4; i++) {
            int t  = tid + i * 256;
            int kr = t >> 5;             // 0..31
            int c4 = (t & 31) << 2;      // 0..124
            float4 bv = *reinterpret_cast<const float4*>(
                W + (size_t)(k0 + kr) * N_FOUT + bn + c4);
            *reinterpret_cast<__half2*>(&Bs[kr][c4 + 0]) = __floats2half2_rn(bv.x, bv.y);
            *reinterpret_cast<__half2*>(&Bs[kr][c4 + 2]) = __floats2half2_rn(bv.z, bv.w);
        }
        __syncthreads();

#pragma unroll
        for (int ks = 0; ks < 2; ks++) {
            const int kk = ks * 16;
            // A fragments: 2 x ldmatrix.x4 (16x16 each)
            uint32_t a[2][4];
#pragma unroll
            for (int mt = 0; mt < 2; mt++) {
                uint32_t addr = as_base +
                    (((wm + mt * 16 + frow) * 40) + kk + fcol) * 2;
                LDSM_X4(a[mt][0], a[mt][1], a[mt][2], a[mt][3], addr);
            }
            // B fragments: 4 x ldmatrix.x4.trans (16k x 16n each -> 2 nt)
            uint32_t b[8][2];
#pragma unroll
            for (int np = 0; np < 4; np++) {
                uint32_t addr = bs_base +
                    (((kk + frow) * 136) + wn + np * 16 + fcol) * 2;
                uint32_t r0, r1, r2, r3;
                LDSM_X4_T(r0, r1, r2, r3, addr);
                b[np * 2 + 0][0] = r0;  // b0: k 0-7 block
                b[np * 2 + 0][1] = r1;  // b1: k 8-15 block
                b[np * 2 + 1][0] = r2;
                b[np * 2 + 1][1] = r3;
            }
#pragma unroll
            for (int mt = 0; mt < 2; mt++)
#pragma unroll
                for (int nt = 0; nt < 8; nt++)
                    mma_f16(acc[mt][nt], a[mt], b[nt][0], b[nt][1]);
        }
        __syncthreads();
    }

    // ---- epilogue: fp16 stores (adjacent column pairs -> __half2) ----
#pragma unroll
    for (int mt = 0; mt < 2; mt++) {
#pragma unroll
        for (int nt = 0; nt < 8; nt++) {
            int r0 = bm + wm + mt * 16 + gid;
            int cc = bn + wn + nt * 8 + 2 * tig;
            if (r0 < M_NODES)
                *reinterpret_cast<__half2*>(&C[(size_t)r0 * N_FOUT + cc]) =
                    __floats2half2_rn(acc[mt][nt][0], acc[mt][nt][1]);
            int r1 = r0 + 8;
            if (r1 < M_NODES)
                *reinterpret_cast<__half2*>(&C[(size_t)r1 * N_FOUT + cc]) =
                    __floats2half2_rn(acc[mt][nt][2], acc[mt][nt][3]);
        }
    }
}

// ---------------------------------------------------------------------------
// CSR construction: count -> scan -> scatter
// ---------------------------------------------------------------------------
__global__ __launch_bounds__(256)
void count_kernel(const int* __restrict__ rows)
{
    int idx = blockIdx.x * blockDim.x + threadIdx.x;
    int stride = gridDim.x * blockDim.x;
    for (int e = idx; e < N_EDGES; e += stride) {
        atomicAdd(&g_row_count[rows[e]], 1);
    }
}

#define SCAN_T 1024
__global__ __launch_bounds__(SCAN_T)
void scan_kernel()
{
    __shared__ int part[SCAN_T];
    const int chunk = (M_NODES + SCAN_T - 1) / SCAN_T;   // 98
    int t = threadIdx.x;
    int begin = t * chunk;
    int end   = begin + chunk;
    if (end > M_NODES) end = M_NODES;
    if (begin > M_NODES) begin = M_NODES;

    int s = 0;
    for (int i = begin; i < end; i++) s += g_row_count[i];
    part[t] = s;
    __syncthreads();

    for (int off = 1; off < SCAN_T; off <<= 1) {
        int v = 0;
        if (t >= off) v = part[t - off];
        __syncthreads();
        part[t] += v;
        __syncthreads();
    }

    int run = (t == 0) ? 0 : part[t - 1];
    for (int i = begin; i < end; i++) {
        g_row_start[i] = run;
        run += g_row_count[i];
    }
    if (t == SCAN_T - 1) g_row_start[M_NODES] = run;
}

__global__ __launch_bounds__(256)
void scatter_kernel(const int*   __restrict__ rows,
                    const int*   __restrict__ cols,
                    const float* __restrict__ vals)
{
    int idx = blockIdx.x * blockDim.x + threadIdx.x;
    int stride = gridDim.x * blockDim.x;
    for (int e = idx; e < N_EDGES; e += stride) {
        int r = rows[e];
        int pos = g_row_start[r] + atomicAdd(&g_row_fill[r], 1);
        g_csr_col[pos] = cols[e];
        g_csr_val[pos] = vals[e];
    }
}

// ---------------------------------------------------------------------------
// Kernel 2: CSR SpMM + fused ReLU (one warp per row), fp16 h.
// ---------------------------------------------------------------------------
__global__ __launch_bounds__(256)
void spmm_csr_kernel(const __half* __restrict__ h,
                     float*        __restrict__ out)
{
    int warp_global = (blockIdx.x * blockDim.x + threadIdx.x) >> 5;
    int lane = threadIdx.x & 31;
    if (warp_global >= M_NODES) return;

    int row = warp_global;
    int s = g_row_start[row];
    int e = g_row_start[row + 1];

    float acc[8];
#pragma unroll
    for (int i = 0; i < 8; i++) acc[i] = 0.f;

    int i = s;
    for (; i + 2 <= e; i += 2) {
        int   c0 = g_csr_col[i];
        float v0 = g_csr_val[i];
        int   c1 = g_csr_col[i + 1];
        float v1 = g_csr_val[i + 1];
        uint4 p0 = __ldg(reinterpret_cast<const uint4*>(h + (size_t)c0 * N_FOUT) + lane);
        uint4 p1 = __ldg(reinterpret_cast<const uint4*>(h + (size_t)c1 * N_FOUT) + lane);
        {
            const __half2* q = reinterpret_cast<const __half2*>(&p0);
#pragma unroll
            for (int j = 0; j < 4; j++) {
                float2 f = __half22float2(q[j]);
                acc[2 * j + 0] += v0 * f.x;
                acc[2 * j + 1] += v0 * f.y;
            }
        }
        {
            const __half2* q = reinterpret_cast<const __half2*>(&p1);
#pragma unroll
            for (int j = 0; j < 4; j++) {
                float2 f = __half22float2(q[j]);
                acc[2 * j + 0] += v1 * f.x;
                acc[2 * j + 1] += v1 * f.y;
            }
        }
    }
    for (; i < e; i++) {
        int   c = g_csr_col[i];
        float v = g_csr_val[i];
        uint4 p = __ldg(reinterpret_cast<const uint4*>(h + (size_t)c * N_FOUT) + lane);
        const __half2* q = reinterpret_cast<const __half2*>(&p);
#pragma unroll
        for (int j = 0; j < 4; j++) {
            float2 f = __half22float2(q[j]);
            acc[2 * j + 0] += v * f.x;
            acc[2 * j + 1] += v * f.y;
        }
    }

    float* orow = out + (size_t)row * N_FOUT + lane * 8;
    float4 o0 = make_float4(fmaxf(acc[0], 0.f), fmaxf(acc[1], 0.f),
                            fmaxf(acc[2], 0.f), fmaxf(acc[3], 0.f));
    float4 o1 = make_float4(fmaxf(acc[4], 0.f), fmaxf(acc[5], 0.f),
                            fmaxf(acc[6], 0.f), fmaxf(acc[7], 0.f));
    *reinterpret_cast<float4*>(orow + 0) = o0;
    *reinterpret_cast<float4*>(orow + 4) = o1;
}

// ---------------------------------------------------------------------------
// Launch: fork GEMM || CSR build, join, SpMM.
// ---------------------------------------------------------------------------
extern "C" void kernel_launch(void* const* d_in, const int* in_sizes, int n_in,
                              void* d_out, int out_size)
{
    const float* x        = (const float*)d_in[0];
    const int*   adj_rows = (const int*)  d_in[1];
    const int*   adj_cols = (const int*)  d_in[2];
    const float* adj_vals = (const float*)d_in[3];
    const float* weight   = (const float*)d_in[4];
    float*       out      = (float*)d_out;

    __half* h = nullptr;
    int*    row_count = nullptr;
    int*    row_fill  = nullptr;
    cudaGetSymbolAddress((void**)&h, g_h);
    cudaGetSymbolAddress((void**)&row_count, g_row_count);
    cudaGetSymbolAddress((void**)&row_fill, g_row_fill);

    static cudaStream_t s2 = nullptr;
    static cudaEvent_t ev_fork = nullptr, ev_join = nullptr;
    if (s2 == nullptr) {
        cudaStreamCreateWithFlags(&s2, cudaStreamNonBlocking);
        cudaEventCreateWithFlags(&ev_fork, cudaEventDisableTiming);
        cudaEventCreateWithFlags(&ev_join, cudaEventDisableTiming);
    }

    // ---- fork: branch B (CSR build) onto s2 ----
    cudaEventRecord(ev_fork, 0);
    cudaStreamWaitEvent(s2, ev_fork, 0);

    cudaMemsetAsync(row_count, 0, M_NODES * sizeof(int), s2);
    cudaMemsetAsync(row_fill,  0, M_NODES * sizeof(int), s2);
    count_kernel<<<1024, 256, 0, s2>>>(adj_rows);
    scan_kernel<<<1, SCAN_T, 0, s2>>>();
    scatter_kernel<<<1024, 256, 0, s2>>>(adj_rows, adj_cols, adj_vals);
    cudaEventRecord(ev_join, s2);

    // Branch A on the main stream: h = x @ W (fp16 HMMA, fp32 accum)
    dim3 ggrid((M_NODES + 127) / 128, N_FOUT / 128);
    hgemm_kernel<<<ggrid, 256>>>(x, weight, h);

    // ---- join, then SpMM ----
    cudaStreamWaitEvent(0, ev_join, 0);
    int nblocks = (M_NODES * 32 + 255) / 256;
    spmm_csr_kernel<<<nblocks, 256>>>(h, out);
}

// round 10
// speedup vs baseline: 2.2898x; 1.0062x over previous
#include <cuda_runtime.h>
#include <cuda_fp16.h>
#include <cuda_bf16.h>
#include <cstddef>
#include <cstdint>

// Problem constants (fixed by the dataset)
#define M_NODES 100000
#define K_FIN   512
#define N_FOUT  256
#define N_EDGES 3200000

// ---------------------------------------------------------------------------
// Static device scratch (no allocations allowed anywhere)
// ---------------------------------------------------------------------------
__device__ __half g_h[(size_t)M_NODES * N_FOUT];       // h = x @ W  (fp16, 51.2 MB)
__device__ int    g_row_count[M_NODES];                // per-row edge counts
__device__ int    g_row_start[M_NODES + 1];            // CSR row offsets
__device__ int    g_row_fill[M_NODES];                 // scatter cursors
__device__ int    g_csr_col[N_EDGES];                  // CSR column indices
__device__ float  g_csr_val[N_EDGES];                  // CSR values

// ---------------------------------------------------------------------------
// fp16 MMA + ldmatrix helpers
// ---------------------------------------------------------------------------
__device__ __forceinline__ void mma_f16(float* c, const uint32_t* a,
                                        uint32_t b0, uint32_t b1) {
    asm volatile(
        "mma.sync.aligned.m16n8k16.row.col.f32.f16.f16.f32 "
        "{%0,%1,%2,%3}, {%4,%5,%6,%7}, {%8,%9}, {%0,%1,%2,%3};\n"
        : "+f"(c[0]), "+f"(c[1]), "+f"(c[2]), "+f"(c[3])
        : "r"(a[0]), "r"(a[1]), "r"(a[2]), "r"(a[3]), "r"(b0), "r"(b1));
}

#define LDSM_X4(r0, r1, r2, r3, addr)                                        \
    asm volatile("ldmatrix.sync.aligned.m8n8.x4.shared.b16 {%0,%1,%2,%3},[%4];" \
                 : "=r"(r0), "=r"(r1), "=r"(r2), "=r"(r3) : "r"(addr))

#define LDSM_X4_T(r0, r1, r2, r3, addr)                                      \
    asm volatile("ldmatrix.sync.aligned.m8n8.x4.trans.shared.b16 {%0,%1,%2,%3},[%4];" \
                 : "=r"(r0), "=r"(r1), "=r"(r2), "=r"(r3) : "r"(addr))

// ---------------------------------------------------------------------------
// Kernel 1: fp16 HMMA GEMM  h[M,256] = x[M,512] @ W[512,256]  (fp32 accum)
// BM=128, BN=128, BK=32; 256 threads = 8 warps (4 m x 2 n), warp tile 32x64,
// mma m16n8k16, fragments via ldmatrix / ldmatrix.trans.
// Software-pipelined: next k-tile's global loads issue before the compute
// phase of the current tile, hiding DRAM/L2 latency (reg double-buffer).
// ---------------------------------------------------------------------------
__global__ __launch_bounds__(256, 2)
void hgemm_kernel(const float* __restrict__ A,   // [M, 512] f32
                  const float* __restrict__ W,   // [512, 256] f32
                  __half* __restrict__ C)        // [M, 256] fp16
{
    __shared__ __align__(16) __half As[128][40];    // 10.0 KB
    __shared__ __align__(16) __half Bs[32][136];    //  8.5 KB

    const int tid  = threadIdx.x;
    const int lane = tid & 31;
    const int warp = tid >> 5;
    const int gid  = lane >> 2;     // 0..7
    const int tig  = lane & 3;      // 0..3
    const int wm   = (warp & 3) * 32;
    const int wn   = (warp >> 2) * 64;
    const int bm   = blockIdx.x * 128;
    const int bn   = blockIdx.y * 128;

    // ldmatrix per-lane source row mapping (matrix idx = lane>>3)
    const int li   = lane >> 3;             // 0..3
    const int l7   = lane & 7;              // 0..7
    const int frow = ((li & 1) << 3) + l7;  // row offset within 16
    const int fcol = (li >> 1) << 3;        // col offset 0 or 8

    const uint32_t as_base = (uint32_t)__cvta_generic_to_shared(&As[0][0]);
    const uint32_t bs_base = (uint32_t)__cvta_generic_to_shared(&Bs[0][0]);

    // Per-thread staging addresses (constant across k-tiles)
    const int a_row  = tid >> 1;                  // 0..127
    const int a_k4_0 = (tid & 1) << 4;            // 0 or 16
    const int gm     = bm + a_row;
    const int b_kr   = tid >> 3;                  // 0..31
    const int b_c4   = (tid & 7) << 4;            // 0,16,...,112
    // A: thread loads 4 float4: row tid>>1, k offsets {a_k4_0 + 4i}
    // B: thread loads 4 float4: k-row tid>>3, col offsets {b_c4 + 4i}

    float4 sa[4], sb[4];

    // ---- preload tile 0 ----
    {
        const float* arow = A + (size_t)gm * K_FIN;
#pragma unroll
        for (int i = 0; i < 4; i++) {
            sa[i] = (gm < M_NODES)
                ? *reinterpret_cast<const float4*>(arow + a_k4_0 + i * 4)
                : make_float4(0.f, 0.f, 0.f, 0.f);
        }
        const float* brow = W + (size_t)b_kr * N_FOUT + bn;
#pragma unroll
        for (int i = 0; i < 4; i++)
            sb[i] = *reinterpret_cast<const float4*>(brow + b_c4 + i * 4);
    }

    float acc[2][8][4];
#pragma unroll
    for (int mt = 0; mt < 2; mt++)
#pragma unroll
        for (int nt = 0; nt < 8; nt++)
#pragma unroll
            for (int i = 0; i < 4; i++) acc[mt][nt][i] = 0.f;

    for (int k0 = 0; k0 < K_FIN; k0 += 32) {
        // ---- store staged regs -> smem (f32 -> f16 convert) ----
#pragma unroll
        for (int i = 0; i < 4; i++) {
            int k4 = a_k4_0 + i * 4;
            *reinterpret_cast<__half2*>(&As[a_row][k4 + 0]) = __floats2half2_rn(sa[i].x, sa[i].y);
            *reinterpret_cast<__half2*>(&As[a_row][k4 + 2]) = __floats2half2_rn(sa[i].z, sa[i].w);
        }
#pragma unroll
        for (int i = 0; i < 4; i++) {
            int c4 = b_c4 + i * 4;
            *reinterpret_cast<__half2*>(&Bs[b_kr][c4 + 0]) = __floats2half2_rn(sb[i].x, sb[i].y);
            *reinterpret_cast<__half2*>(&Bs[b_kr][c4 + 2]) = __floats2half2_rn(sb[i].z, sb[i].w);
        }
        __syncthreads();

        // ---- issue NEXT tile's global loads (overlap with compute below) ----
        int k1 = k0 + 32;
        if (k1 < K_FIN) {
            const float* arow = A + (size_t)gm * K_FIN + k1;
#pragma unroll
            for (int i = 0; i < 4; i++) {
                sa[i] = (gm < M_NODES)
                    ? *reinterpret_cast<const float4*>(arow + a_k4_0 + i * 4)
                    : make_float4(0.f, 0.f, 0.f, 0.f);
            }
            const float* brow = W + (size_t)(k1 + b_kr) * N_FOUT + bn;
#pragma unroll
            for (int i = 0; i < 4; i++)
                sb[i] = *reinterpret_cast<const float4*>(brow + b_c4 + i * 4);
        }

        // ---- compute from smem ----
#pragma unroll
        for (int ks = 0; ks < 2; ks++) {
            const int kk = ks * 16;
            uint32_t a[2][4];
#pragma unroll
            for (int mt = 0; mt < 2; mt++) {
                uint32_t addr = as_base +
                    (((wm + mt * 16 + frow) * 40) + kk + fcol) * 2;
                LDSM_X4(a[mt][0], a[mt][1], a[mt][2], a[mt][3], addr);
            }
            uint32_t b[8][2];
#pragma unroll
            for (int np = 0; np < 4; np++) {
                uint32_t addr = bs_base +
                    (((kk + frow) * 136) + wn + np * 16 + fcol) * 2;
                uint32_t r0, r1, r2, r3;
                LDSM_X4_T(r0, r1, r2, r3, addr);
                b[np * 2 + 0][0] = r0;
                b[np * 2 + 0][1] = r1;
                b[np * 2 + 1][0] = r2;
                b[np * 2 + 1][1] = r3;
            }
#pragma unroll
            for (int mt = 0; mt < 2; mt++)
#pragma unroll
                for (int nt = 0; nt < 8; nt++)
                    mma_f16(acc[mt][nt], a[mt], b[nt][0], b[nt][1]);
        }
        __syncthreads();
    }

    // ---- epilogue: fp16 stores (adjacent column pairs -> __half2) ----
#pragma unroll
    for (int mt = 0; mt < 2; mt++) {
#pragma unroll
        for (int nt = 0; nt < 8; nt++) {
            int r0 = bm + wm + mt * 16 + gid;
            int cc = bn + wn + nt * 8 + 2 * tig;
            if (r0 < M_NODES)
                *reinterpret_cast<__half2*>(&C[(size_t)r0 * N_FOUT + cc]) =
                    __floats2half2_rn(acc[mt][nt][0], acc[mt][nt][1]);
            int r1 = r0 + 8;
            if (r1 < M_NODES)
                *reinterpret_cast<__half2*>(&C[(size_t)r1 * N_FOUT + cc]) =
                    __floats2half2_rn(acc[mt][nt][2], acc[mt][nt][3]);
        }
    }
}

// ---------------------------------------------------------------------------
// CSR construction: count -> scan -> scatter
// ---------------------------------------------------------------------------
__global__ __launch_bounds__(256)
void count_kernel(const int* __restrict__ rows)
{
    int idx = blockIdx.x * blockDim.x + threadIdx.x;
    int stride = gridDim.x * blockDim.x;
    for (int e = idx; e < N_EDGES; e += stride) {
        atomicAdd(&g_row_count[rows[e]], 1);
    }
}

#define SCAN_T 1024
__global__ __launch_bounds__(SCAN_T)
void scan_kernel()
{
    __shared__ int part[SCAN_T];
    const int chunk = (M_NODES + SCAN_T - 1) / SCAN_T;   // 98
    int t = threadIdx.x;
    int begin = t * chunk;
    int end   = begin + chunk;
    if (end > M_NODES) end = M_NODES;
    if (begin > M_NODES) begin = M_NODES;

    int s = 0;
    for (int i = begin; i < end; i++) s += g_row_count[i];
    part[t] = s;
    __syncthreads();

    for (int off = 1; off < SCAN_T; off <<= 1) {
        int v = 0;
        if (t >= off) v = part[t - off];
        __syncthreads();
        part[t] += v;
        __syncthreads();
    }

    int run = (t == 0) ? 0 : part[t - 1];
    for (int i = begin; i < end; i++) {
        g_row_start[i] = run;
        run += g_row_count[i];
    }
    if (t == SCAN_T - 1) g_row_start[M_NODES] = run;
}

__global__ __launch_bounds__(256)
void scatter_kernel(const int*   __restrict__ rows,
                    const int*   __restrict__ cols,
                    const float* __restrict__ vals)
{
    int idx = blockIdx.x * blockDim.x + threadIdx.x;
    int stride = gridDim.x * blockDim.x;
    for (int e = idx; e < N_EDGES; e += stride) {
        int r = rows[e];
        int pos = g_row_start[r] + atomicAdd(&g_row_fill[r], 1);
        g_csr_col[pos] = cols[e];
        g_csr_val[pos] = vals[e];
    }
}

// ---------------------------------------------------------------------------
// Kernel 2: CSR SpMM + fused ReLU (one warp per row), fp16 h.
// ---------------------------------------------------------------------------
__global__ __launch_bounds__(256)
void spmm_csr_kernel(const __half* __restrict__ h,
                     float*        __restrict__ out)
{
    int warp_global = (blockIdx.x * blockDim.x + threadIdx.x) >> 5;
    int lane = threadIdx.x & 31;
    if (warp_global >= M_NODES) return;

    int row = warp_global;
    int s = g_row_start[row];
    int e = g_row_start[row + 1];

    float acc[8];
#pragma unroll
    for (int i = 0; i < 8; i++) acc[i] = 0.f;

    int i = s;
    for (; i + 2 <= e; i += 2) {
        int   c0 = g_csr_col[i];
        float v0 = g_csr_val[i];
        int   c1 = g_csr_col[i + 1];
        float v1 = g_csr_val[i + 1];
        uint4 p0 = __ldg(reinterpret_cast<const uint4*>(h + (size_t)c0 * N_FOUT) + lane);
        uint4 p1 = __ldg(reinterpret_cast<const uint4*>(h + (size_t)c1 * N_FOUT) + lane);
        {
            const __half2* q = reinterpret_cast<const __half2*>(&p0);
#pragma unroll
            for (int j = 0; j < 4; j++) {
                float2 f = __half22float2(q[j]);
                acc[2 * j + 0] += v0 * f.x;
                acc[2 * j + 1] += v0 * f.y;
            }
        }
        {
            const __half2* q = reinterpret_cast<const __half2*>(&p1);
#pragma unroll
            for (int j = 0; j < 4; j++) {
                float2 f = __half22float2(q[j]);
                acc[2 * j + 0] += v1 * f.x;
                acc[2 * j + 1] += v1 * f.y;
            }
        }
    }
    for (; i < e; i++) {
        int   c = g_csr_col[i];
        float v = g_csr_val[i];
        uint4 p = __ldg(reinterpret_cast<const uint4*>(h + (size_t)c * N_FOUT) + lane);
        const __half2* q = reinterpret_cast<const __half2*>(&p);
#pragma unroll
        for (int j = 0; j < 4; j++) {
            float2 f = __half22float2(q[j]);
            acc[2 * j + 0] += v * f.x;
            acc[2 * j + 1] += v * f.y;
        }
    }

    float* orow = out + (size_t)row * N_FOUT + lane * 8;
    float4 o0 = make_float4(fmaxf(acc[0], 0.f), fmaxf(acc[1], 0.f),
                            fmaxf(acc[2], 0.f), fmaxf(acc[3], 0.f));
    float4 o1 = make_float4(fmaxf(acc[4], 0.f), fmaxf(acc[5], 0.f),
                            fmaxf(acc[6], 0.f), fmaxf(acc[7], 0.f));
    *reinterpret_cast<float4*>(orow + 0) = o0;
    *reinterpret_cast<float4*>(orow + 4) = o1;
}

// ---------------------------------------------------------------------------
// Launch: fork GEMM || CSR build, join, SpMM.
// ---------------------------------------------------------------------------
extern "C" void kernel_launch(void* const* d_in, const int* in_sizes, int n_in,
                              void* d_out, int out_size)
{
    const float* x        = (const float*)d_in[0];
    const int*   adj_rows = (const int*)  d_in[1];
    const int*   adj_cols = (const int*)  d_in[2];
    const float* adj_vals = (const float*)d_in[3];
    const float* weight   = (const float*)d_in[4];
    float*       out      = (float*)d_out;

    __half* h = nullptr;
    int*    row_count = nullptr;
    int*    row_fill  = nullptr;
    cudaGetSymbolAddress((void**)&h, g_h);
    cudaGetSymbolAddress((void**)&row_count, g_row_count);
    cudaGetSymbolAddress((void**)&row_fill, g_row_fill);

    static cudaStream_t s2 = nullptr;
    static cudaEvent_t ev_fork = nullptr, ev_join = nullptr;
    if (s2 == nullptr) {
        cudaStreamCreateWithFlags(&s2, cudaStreamNonBlocking);
        cudaEventCreateWithFlags(&ev_fork, cudaEventDisableTiming);
        cudaEventCreateWithFlags(&ev_join, cudaEventDisableTiming);
    }

    // ---- fork: branch B (CSR build) onto s2 ----
    cudaEventRecord(ev_fork, 0);
    cudaStreamWaitEvent(s2, ev_fork, 0);

    cudaMemsetAsync(row_count, 0, M_NODES * sizeof(int), s2);
    cudaMemsetAsync(row_fill,  0, M_NODES * sizeof(int), s2);
    count_kernel<<<1024, 256, 0, s2>>>(adj_rows);
    scan_kernel<<<1, SCAN_T, 0, s2>>>();
    scatter_kernel<<<1024, 256, 0, s2>>>(adj_rows, adj_cols, adj_vals);
    cudaEventRecord(ev_join, s2);

    // Branch A on the main stream: h = x @ W (fp16 HMMA, reg-pipelined)
    dim3 ggrid((M_NODES + 127) / 128, N_FOUT / 128);
    hgemm_kernel<<<ggrid, 256>>>(x, weight, h);

    // ---- join, then SpMM ----
    cudaStreamWaitEvent(0, ev_join, 0);
    int nblocks = (M_NODES * 32 + 255) / 256;
    spmm_csr_kernel<<<nblocks, 256>>>(h, out);
}

// round 12
// speedup vs baseline: 2.9564x; 1.2911x over previous
#include <cuda_runtime.h>
#include <cuda_fp16.h>
#include <cuda_bf16.h>
#include <cstddef>
#include <cstdint>

// Problem constants (fixed by the dataset)
#define M_NODES 100000
#define K_FIN   512
#define N_FOUT  256
#define N_EDGES 3200000

// ---------------------------------------------------------------------------
// Static device scratch (no allocations allowed anywhere)
// ---------------------------------------------------------------------------
__device__ __half g_xh[(size_t)M_NODES * K_FIN];       // x in fp16 (102.4 MB)
__device__ __half g_wh[K_FIN * N_FOUT];                // W in fp16 (0.25 MB)
__device__ __half g_h[(size_t)M_NODES * N_FOUT];       // h = x @ W  (51.2 MB)
__device__ int    g_row_count[M_NODES];
__device__ int    g_row_start[M_NODES + 1];
__device__ int    g_row_fill[M_NODES];
__device__ int    g_csr_col[N_EDGES];
__device__ float  g_csr_val[N_EDGES];

// ---------------------------------------------------------------------------
// fp16 MMA + ldmatrix helpers
// ---------------------------------------------------------------------------
__device__ __forceinline__ void mma_f16(float* c, const uint32_t* a,
                                        uint32_t b0, uint32_t b1) {
    asm volatile(
        "mma.sync.aligned.m16n8k16.row.col.f32.f16.f16.f32 "
        "{%0,%1,%2,%3}, {%4,%5,%6,%7}, {%8,%9}, {%0,%1,%2,%3};\n"
        : "+f"(c[0]), "+f"(c[1]), "+f"(c[2]), "+f"(c[3])
        : "r"(a[0]), "r"(a[1]), "r"(a[2]), "r"(a[3]), "r"(b0), "r"(b1));
}

#define LDSM_X4(r0, r1, r2, r3, addr)                                        \
    asm volatile("ldmatrix.sync.aligned.m8n8.x4.shared.b16 {%0,%1,%2,%3},[%4];" \
                 : "=r"(r0), "=r"(r1), "=r"(r2), "=r"(r3) : "r"(addr))

#define LDSM_X4_T(r0, r1, r2, r3, addr)                                      \
    asm volatile("ldmatrix.sync.aligned.m8n8.x4.trans.shared.b16 {%0,%1,%2,%3},[%4];" \
                 : "=r"(r0), "=r"(r1), "=r"(r2), "=r"(r3) : "r"(addr))

// ---------------------------------------------------------------------------
// Conversion kernels: f32 -> f16 (one pass, outside the GEMM hot loop)
// ---------------------------------------------------------------------------
__global__ __launch_bounds__(256)
void convert_x_kernel(const float* __restrict__ in, __half* __restrict__ out)
{
    const size_t total4 = (size_t)M_NODES * K_FIN / 4;
    size_t idx = (size_t)blockIdx.x * blockDim.x + threadIdx.x;
    size_t stride = (size_t)gridDim.x * blockDim.x;
    __half2* out2 = reinterpret_cast<__half2*>(out);
    for (size_t i = idx; i < total4; i += stride) {
        float4 v = reinterpret_cast<const float4*>(in)[i];
        out2[2 * i + 0] = __floats2half2_rn(v.x, v.y);
        out2[2 * i + 1] = __floats2half2_rn(v.z, v.w);
    }
}

__global__ __launch_bounds__(256)
void convert_w_kernel(const float* __restrict__ in, __half* __restrict__ out)
{
    const int total4 = K_FIN * N_FOUT / 4;
    int idx = blockIdx.x * blockDim.x + threadIdx.x;
    int stride = gridDim.x * blockDim.x;
    __half2* out2 = reinterpret_cast<__half2*>(out);
    for (int i = idx; i < total4; i += stride) {
        float4 v = reinterpret_cast<const float4*>(in)[i];
        out2[2 * i + 0] = __floats2half2_rn(v.x, v.y);
        out2[2 * i + 1] = __floats2half2_rn(v.z, v.w);
    }
}

// ---------------------------------------------------------------------------
// Kernel 1: fp16 HMMA GEMM  h[M,256] = xh[M,512] @ wh[512,256]  (fp32 accum)
// BM=128, BN=128, BK=32; 256 threads = 8 warps (4 m x 2 n), warp tile 32x64.
// fp16 inputs: staging is pure copy (2 LDG.128 + 2 STS.128 per matrix per
// thread per tile), register-prefetched one tile ahead.
// ---------------------------------------------------------------------------
__global__ __launch_bounds__(256, 2)
void hgemm_kernel(const __half* __restrict__ A,   // [M, 512] f16
                  const __half* __restrict__ W,   // [512, 256] f16
                  __half* __restrict__ C)         // [M, 256] f16
{
    __shared__ __align__(16) __half As[128][40];    // 10.0 KB
    __shared__ __align__(16) __half Bs[32][136];    //  8.5 KB

    const int tid  = threadIdx.x;
    const int lane = tid & 31;
    const int warp = tid >> 5;
    const int gid  = lane >> 2;     // 0..7
    const int tig  = lane & 3;      // 0..3
    const int wm   = (warp & 3) * 32;
    const int wn   = (warp >> 2) * 64;
    const int bm   = blockIdx.x * 128;
    const int bn   = blockIdx.y * 128;

    // ldmatrix per-lane source row mapping
    const int li   = lane >> 3;
    const int l7   = lane & 7;
    const int frow = ((li & 1) << 3) + l7;
    const int fcol = (li >> 1) << 3;

    const uint32_t as_base = (uint32_t)__cvta_generic_to_shared(&As[0][0]);
    const uint32_t bs_base = (uint32_t)__cvta_generic_to_shared(&Bs[0][0]);

    // Staging map: A thread -> row tid>>1, 16-half chunk (tid&1)*16
    //              B thread -> k-row tid>>3, 16-half chunk (tid&7)*16
    const int a_row = tid >> 1;
    const int a_h0  = (tid & 1) << 4;
    const int gm    = bm + a_row;
    const int b_kr  = tid >> 3;
    const int b_h0  = (tid & 7) << 4;

    uint4 pa[2], pb[2];

    // ---- preload tile 0 ----
    {
        const __half* ap = A + (size_t)gm * K_FIN + a_h0;
        if (gm < M_NODES) {
            pa[0] = *reinterpret_cast<const uint4*>(ap);
            pa[1] = *reinterpret_cast<const uint4*>(ap + 8);
        } else {
            pa[0] = make_uint4(0, 0, 0, 0);
            pa[1] = make_uint4(0, 0, 0, 0);
        }
        const __half* bp = W + (size_t)b_kr * N_FOUT + bn + b_h0;
        pb[0] = *reinterpret_cast<const uint4*>(bp);
        pb[1] = *reinterpret_cast<const uint4*>(bp + 8);
    }

    float acc[2][8][4];
#pragma unroll
    for (int mt = 0; mt < 2; mt++)
#pragma unroll
        for (int nt = 0; nt < 8; nt++)
#pragma unroll
            for (int i = 0; i < 4; i++) acc[mt][nt][i] = 0.f;

    for (int k0 = 0; k0 < K_FIN; k0 += 32) {
        // ---- store staged regs -> smem (pure copy, STS.128) ----
        *reinterpret_cast<uint4*>(&As[a_row][a_h0 + 0]) = pa[0];
        *reinterpret_cast<uint4*>(&As[a_row][a_h0 + 8]) = pa[1];
        *reinterpret_cast<uint4*>(&Bs[b_kr][b_h0 + 0]) = pb[0];
        *reinterpret_cast<uint4*>(&Bs[b_kr][b_h0 + 8]) = pb[1];
        __syncthreads();

        // ---- issue NEXT tile's global loads ----
        int k1 = k0 + 32;
        if (k1 < K_FIN) {
            const __half* ap = A + (size_t)gm * K_FIN + k1 + a_h0;
            if (gm < M_NODES) {
                pa[0] = *reinterpret_cast<const uint4*>(ap);
                pa[1] = *reinterpret_cast<const uint4*>(ap + 8);
            } else {
                pa[0] = make_uint4(0, 0, 0, 0);
                pa[1] = make_uint4(0, 0, 0, 0);
            }
            const __half* bp = W + (size_t)(k1 + b_kr) * N_FOUT + bn + b_h0;
            pb[0] = *reinterpret_cast<const uint4*>(bp);
            pb[1] = *reinterpret_cast<const uint4*>(bp + 8);
        }

        // ---- compute from smem ----
#pragma unroll
        for (int ks = 0; ks < 2; ks++) {
            const int kk = ks * 16;
            uint32_t a[2][4];
#pragma unroll
            for (int mt = 0; mt < 2; mt++) {
                uint32_t addr = as_base +
                    (((wm + mt * 16 + frow) * 40) + kk + fcol) * 2;
                LDSM_X4(a[mt][0], a[mt][1], a[mt][2], a[mt][3], addr);
            }
            uint32_t b[8][2];
#pragma unroll
            for (int np = 0; np < 4; np++) {
                uint32_t addr = bs_base +
                    (((kk + frow) * 136) + wn + np * 16 + fcol) * 2;
                uint32_t r0, r1, r2, r3;
                LDSM_X4_T(r0, r1, r2, r3, addr);
                b[np * 2 + 0][0] = r0;
                b[np * 2 + 0][1] = r1;
                b[np * 2 + 1][0] = r2;
                b[np * 2 + 1][1] = r3;
            }
#pragma unroll
            for (int mt = 0; mt < 2; mt++)
#pragma unroll
                for (int nt = 0; nt < 8; nt++)
                    mma_f16(acc[mt][nt], a[mt], b[nt][0], b[nt][1]);
        }
        __syncthreads();
    }

    // ---- epilogue: fp16 stores ----
#pragma unroll
    for (int mt = 0; mt < 2; mt++) {
#pragma unroll
        for (int nt = 0; nt < 8; nt++) {
            int r0 = bm + wm + mt * 16 + gid;
            int cc = bn + wn + nt * 8 + 2 * tig;
            if (r0 < M_NODES)
                *reinterpret_cast<__half2*>(&C[(size_t)r0 * N_FOUT + cc]) =
                    __floats2half2_rn(acc[mt][nt][0], acc[mt][nt][1]);
            int r1 = r0 + 8;
            if (r1 < M_NODES)
                *reinterpret_cast<__half2*>(&C[(size_t)r1 * N_FOUT + cc]) =
                    __floats2half2_rn(acc[mt][nt][2], acc[mt][nt][3]);
        }
    }
}

// ---------------------------------------------------------------------------
// CSR construction: count -> scan -> scatter
// ---------------------------------------------------------------------------
__global__ __launch_bounds__(256)
void count_kernel(const int* __restrict__ rows)
{
    int idx = blockIdx.x * blockDim.x + threadIdx.x;
    int stride = gridDim.x * blockDim.x;
    for (int e = idx; e < N_EDGES; e += stride) {
        atomicAdd(&g_row_count[rows[e]], 1);
    }
}

#define SCAN_T 1024
__global__ __launch_bounds__(SCAN_T)
void scan_kernel()
{
    __shared__ int part[SCAN_T];
    const int chunk = (M_NODES + SCAN_T - 1) / SCAN_T;
    int t = threadIdx.x;
    int begin = t * chunk;
    int end   = begin + chunk;
    if (end > M_NODES) end = M_NODES;
    if (begin > M_NODES) begin = M_NODES;

    int s = 0;
    for (int i = begin; i < end; i++) s += g_row_count[i];
    part[t] = s;
    __syncthreads();

    for (int off = 1; off < SCAN_T; off <<= 1) {
        int v = 0;
        if (t >= off) v = part[t - off];
        __syncthreads();
        part[t] += v;
        __syncthreads();
    }

    int run = (t == 0) ? 0 : part[t - 1];
    for (int i = begin; i < end; i++) {
        g_row_start[i] = run;
        run += g_row_count[i];
    }
    if (t == SCAN_T - 1) g_row_start[M_NODES] = run;
}

__global__ __launch_bounds__(256)
void scatter_kernel(const int*   __restrict__ rows,
                    const int*   __restrict__ cols,
                    const float* __restrict__ vals)
{
    int idx = blockIdx.x * blockDim.x + threadIdx.x;
    int stride = gridDim.x * blockDim.x;
    for (int e = idx; e < N_EDGES; e += stride) {
        int r = rows[e];
        int pos = g_row_start[r] + atomicAdd(&g_row_fill[r], 1);
        g_csr_col[pos] = cols[e];
        g_csr_val[pos] = vals[e];
    }
}

// ---------------------------------------------------------------------------
// Kernel 2: CSR SpMM + fused ReLU (one warp per row), fp16 h.
// ---------------------------------------------------------------------------
__global__ __launch_bounds__(256)
void spmm_csr_kernel(const __half* __restrict__ h,
                     float*        __restrict__ out)
{
    int warp_global = (blockIdx.x * blockDim.x + threadIdx.x) >> 5;
    int lane = threadIdx.x & 31;
    if (warp_global >= M_NODES) return;

    int row = warp_global;
    int s = g_row_start[row];
    int e = g_row_start[row + 1];

    float acc[8];
#pragma unroll
    for (int i = 0; i < 8; i++) acc[i] = 0.f;

    int i = s;
    for (; i + 2 <= e; i += 2) {
        int   c0 = g_csr_col[i];
        float v0 = g_csr_val[i];
        int   c1 = g_csr_col[i + 1];
        float v1 = g_csr_val[i + 1];
        uint4 p0 = __ldg(reinterpret_cast<const uint4*>(h + (size_t)c0 * N_FOUT) + lane);
        uint4 p1 = __ldg(reinterpret_cast<const uint4*>(h + (size_t)c1 * N_FOUT) + lane);
        {
            const __half2* q = reinterpret_cast<const __half2*>(&p0);
#pragma unroll
            for (int j = 0; j < 4; j++) {
                float2 f = __half22float2(q[j]);
                acc[2 * j + 0] += v0 * f.x;
                acc[2 * j + 1] += v0 * f.y;
            }
        }
        {
            const __half2* q = reinterpret_cast<const __half2*>(&p1);
#pragma unroll
            for (int j = 0; j < 4; j++) {
                float2 f = __half22float2(q[j]);
                acc[2 * j + 0] += v1 * f.x;
                acc[2 * j + 1] += v1 * f.y;
            }
        }
    }
    for (; i < e; i++) {
        int   c = g_csr_col[i];
        float v = g_csr_val[i];
        uint4 p = __ldg(reinterpret_cast<const uint4*>(h + (size_t)c * N_FOUT) + lane);
        const __half2* q = reinterpret_cast<const __half2*>(&p);
#pragma unroll
        for (int j = 0; j < 4; j++) {
            float2 f = __half22float2(q[j]);
            acc[2 * j + 0] += v * f.x;
            acc[2 * j + 1] += v * f.y;
        }
    }

    float* orow = out + (size_t)row * N_FOUT + lane * 8;
    float4 o0 = make_float4(fmaxf(acc[0], 0.f), fmaxf(acc[1], 0.f),
                            fmaxf(acc[2], 0.f), fmaxf(acc[3], 0.f));
    float4 o1 = make_float4(fmaxf(acc[4], 0.f), fmaxf(acc[5], 0.f),
                            fmaxf(acc[6], 0.f), fmaxf(acc[7], 0.f));
    *reinterpret_cast<float4*>(orow + 0) = o0;
    *reinterpret_cast<float4*>(orow + 4) = o1;
}

// ---------------------------------------------------------------------------
// Launch: s1: convert W,x -> fp16 GEMM ; s2 (forked): CSR build ; join ; SpMM
// ---------------------------------------------------------------------------
extern "C" void kernel_launch(void* const* d_in, const int* in_sizes, int n_in,
                              void* d_out, int out_size)
{
    const float* x        = (const float*)d_in[0];
    const int*   adj_rows = (const int*)  d_in[1];
    const int*   adj_cols = (const int*)  d_in[2];
    const float* adj_vals = (const float*)d_in[3];
    const float* weight   = (const float*)d_in[4];
    float*       out      = (float*)d_out;

    __half* xh = nullptr;
    __half* wh = nullptr;
    __half* h  = nullptr;
    int*    row_count = nullptr;
    int*    row_fill  = nullptr;
    cudaGetSymbolAddress((void**)&xh, g_xh);
    cudaGetSymbolAddress((void**)&wh, g_wh);
    cudaGetSymbolAddress((void**)&h,  g_h);
    cudaGetSymbolAddress((void**)&row_count, g_row_count);
    cudaGetSymbolAddress((void**)&row_fill, g_row_fill);

    static cudaStream_t s2 = nullptr;
    static cudaEvent_t ev_fork = nullptr, ev_join = nullptr;
    if (s2 == nullptr) {
        cudaStreamCreateWithFlags(&s2, cudaStreamNonBlocking);
        cudaEventCreateWithFlags(&ev_fork, cudaEventDisableTiming);
        cudaEventCreateWithFlags(&ev_join, cudaEventDisableTiming);
    }

    // ---- fork: branch B (CSR build) onto s2 ----
    cudaEventRecord(ev_fork, 0);
    cudaStreamWaitEvent(s2, ev_fork, 0);

    cudaMemsetAsync(row_count, 0, M_NODES * sizeof(int), s2);
    cudaMemsetAsync(row_fill,  0, M_NODES * sizeof(int), s2);
    count_kernel<<<1024, 256, 0, s2>>>(adj_rows);
    scan_kernel<<<1, SCAN_T, 0, s2>>>();
    scatter_kernel<<<1024, 256, 0, s2>>>(adj_rows, adj_cols, adj_vals);
    cudaEventRecord(ev_join, s2);

    // Branch A on the main stream: convert to fp16, then GEMM
    convert_w_kernel<<<64, 256>>>(weight, wh);
    convert_x_kernel<<<2048, 256>>>(x, xh);
    dim3 ggrid((M_NODES + 127) / 128, N_FOUT / 128);
    hgemm_kernel<<<ggrid, 256>>>(xh, wh, h);

    // ---- join, then SpMM ----
    cudaStreamWaitEvent(0, ev_join, 0);
    int nblocks = (M_NODES * 32 + 255) / 256;
    spmm_csr_kernel<<<nblocks, 256>>>(h, out);
}

// round 13
// speedup vs baseline: 2.9936x; 1.0126x over previous
#include <cuda_runtime.h>
#include <cuda_fp16.h>
#include <cuda_bf16.h>
#include <cstddef>
#include <cstdint>

// Problem constants (fixed by the dataset)
#define M_NODES 100000
#define K_FIN   512
#define N_FOUT  256
#define N_EDGES 3200000

// ---------------------------------------------------------------------------
// Static device scratch (no allocations allowed anywhere)
// ---------------------------------------------------------------------------
__device__ __half g_xh[(size_t)M_NODES * K_FIN];       // x in fp16 (102.4 MB)
__device__ __half g_wh[K_FIN * N_FOUT];                // W in fp16 (0.25 MB)
__device__ __half g_h[(size_t)M_NODES * N_FOUT];       // h = x @ W  (51.2 MB)
__device__ int    g_row_count[M_NODES];
__device__ int    g_row_start[M_NODES + 1];
__device__ int    g_row_fill[M_NODES];
__device__ int    g_csr_col[N_EDGES];
__device__ float  g_csr_val[N_EDGES];

// ---------------------------------------------------------------------------
// fp16 MMA + ldmatrix helpers
// ---------------------------------------------------------------------------
__device__ __forceinline__ void mma_f16(float* c, const uint32_t* a,
                                        uint32_t b0, uint32_t b1) {
    asm volatile(
        "mma.sync.aligned.m16n8k16.row.col.f32.f16.f16.f32 "
        "{%0,%1,%2,%3}, {%4,%5,%6,%7}, {%8,%9}, {%0,%1,%2,%3};\n"
        : "+f"(c[0]), "+f"(c[1]), "+f"(c[2]), "+f"(c[3])
        : "r"(a[0]), "r"(a[1]), "r"(a[2]), "r"(a[3]), "r"(b0), "r"(b1));
}

#define LDSM_X4(r0, r1, r2, r3, addr)                                        \
    asm volatile("ldmatrix.sync.aligned.m8n8.x4.shared.b16 {%0,%1,%2,%3},[%4];" \
                 : "=r"(r0), "=r"(r1), "=r"(r2), "=r"(r3) : "r"(addr))

#define LDSM_X4_T(r0, r1, r2, r3, addr)                                      \
    asm volatile("ldmatrix.sync.aligned.m8n8.x4.trans.shared.b16 {%0,%1,%2,%3},[%4];" \
                 : "=r"(r0), "=r"(r1), "=r"(r2), "=r"(r3) : "r"(addr))

// ---------------------------------------------------------------------------
// Conversion kernels: f32 -> f16
// ---------------------------------------------------------------------------
__global__ __launch_bounds__(256)
void convert_x_kernel(const float* __restrict__ in, __half* __restrict__ out)
{
    const size_t total4 = (size_t)M_NODES * K_FIN / 4;
    size_t idx = (size_t)blockIdx.x * blockDim.x + threadIdx.x;
    size_t stride = (size_t)gridDim.x * blockDim.x;
    __half2* out2 = reinterpret_cast<__half2*>(out);
    for (size_t i = idx; i < total4; i += stride) {
        float4 v = reinterpret_cast<const float4*>(in)[i];
        out2[2 * i + 0] = __floats2half2_rn(v.x, v.y);
        out2[2 * i + 1] = __floats2half2_rn(v.z, v.w);
    }
}

__global__ __launch_bounds__(256)
void convert_w_kernel(const float* __restrict__ in, __half* __restrict__ out)
{
    const int total4 = K_FIN * N_FOUT / 4;
    int idx = blockIdx.x * blockDim.x + threadIdx.x;
    int stride = gridDim.x * blockDim.x;
    __half2* out2 = reinterpret_cast<__half2*>(out);
    for (int i = idx; i < total4; i += stride) {
        float4 v = reinterpret_cast<const float4*>(in)[i];
        out2[2 * i + 0] = __floats2half2_rn(v.x, v.y);
        out2[2 * i + 1] = __floats2half2_rn(v.z, v.w);
    }
}

// ---------------------------------------------------------------------------
// Kernel 1: fp16 HMMA GEMM  h[M,256] = xh[M,512] @ wh[512,256]  (fp32 accum)
// BM=128, BN=128, BK=64; 256 threads = 8 warps (4 m x 2 n), warp tile 32x64,
// mma m16n8k16, fragments via ldmatrix / ldmatrix.trans.
// BK=64 halves sync count vs BK=32. No register prefetch (L1-bound).
// As row stride 72 halves (36 words): STS.128 / LDSM phases conflict-free.
// ---------------------------------------------------------------------------
__global__ __launch_bounds__(256, 2)
void hgemm_kernel(const __half* __restrict__ A,   // [M, 512] f16
                  const __half* __restrict__ W,   // [512, 256] f16
                  __half* __restrict__ C)         // [M, 256] f16
{
    __shared__ __align__(16) __half As[128][72];    // 18.0 KB
    __shared__ __align__(16) __half Bs[64][136];    // 17.0 KB

    const int tid  = threadIdx.x;
    const int lane = tid & 31;
    const int warp = tid >> 5;
    const int gid  = lane >> 2;     // 0..7
    const int tig  = lane & 3;      // 0..3
    const int wm   = (warp & 3) * 32;
    const int wn   = (warp >> 2) * 64;
    const int bm   = blockIdx.x * 128;
    const int bn   = blockIdx.y * 128;

    // ldmatrix per-lane source row mapping
    const int li   = lane >> 3;
    const int l7   = lane & 7;
    const int frow = ((li & 1) << 3) + l7;
    const int fcol = (li >> 1) << 3;

    const uint32_t as_base = (uint32_t)__cvta_generic_to_shared(&As[0][0]);
    const uint32_t bs_base = (uint32_t)__cvta_generic_to_shared(&Bs[0][0]);

    // Staging map (BK=64):
    // A: thread -> rows {tid>>2, tid>>2 + 64}, 16-half chunk (tid&3)*16
    // B: thread -> k-rows {tid>>3, tid>>3 + 32}, 16-half chunk (tid&7)*16
    const int a_row = tid >> 2;
    const int a_h0  = (tid & 3) << 4;
    const int b_kr  = tid >> 3;
    const int b_h0  = (tid & 7) << 4;

    float acc[2][8][4];
#pragma unroll
    for (int mt = 0; mt < 2; mt++)
#pragma unroll
        for (int nt = 0; nt < 8; nt++)
#pragma unroll
            for (int i = 0; i < 4; i++) acc[mt][nt][i] = 0.f;

    for (int k0 = 0; k0 < K_FIN; k0 += 64) {
        // ---- stage A: 2 half-rows per thread ----
#pragma unroll
        for (int i = 0; i < 2; i++) {
            int row = a_row + i * 64;
            int gm  = bm + row;
            uint4 v0, v1;
            if (gm < M_NODES) {
                const __half* ap = A + (size_t)gm * K_FIN + k0 + a_h0;
                v0 = *reinterpret_cast<const uint4*>(ap);
                v1 = *reinterpret_cast<const uint4*>(ap + 8);
            } else {
                v0 = make_uint4(0, 0, 0, 0);
                v1 = make_uint4(0, 0, 0, 0);
            }
            *reinterpret_cast<uint4*>(&As[row][a_h0 + 0]) = v0;
            *reinterpret_cast<uint4*>(&As[row][a_h0 + 8]) = v1;
        }
        // ---- stage B: 2 chunks per thread ----
#pragma unroll
        for (int i = 0; i < 2; i++) {
            int kr = b_kr + i * 32;
            const __half* bp = W + (size_t)(k0 + kr) * N_FOUT + bn + b_h0;
            uint4 v0 = *reinterpret_cast<const uint4*>(bp);
            uint4 v1 = *reinterpret_cast<const uint4*>(bp + 8);
            *reinterpret_cast<uint4*>(&Bs[kr][b_h0 + 0]) = v0;
            *reinterpret_cast<uint4*>(&Bs[kr][b_h0 + 8]) = v1;
        }
        __syncthreads();

        // ---- compute: 4 k-groups of 16 ----
#pragma unroll
        for (int ks = 0; ks < 4; ks++) {
            const int kk = ks * 16;
            uint32_t a[2][4];
#pragma unroll
            for (int mt = 0; mt < 2; mt++) {
                uint32_t addr = as_base +
                    (((wm + mt * 16 + frow) * 72) + kk + fcol) * 2;
                LDSM_X4(a[mt][0], a[mt][1], a[mt][2], a[mt][3], addr);
            }
            uint32_t b[8][2];
#pragma unroll
            for (int np = 0; np < 4; np++) {
                uint32_t addr = bs_base +
                    (((kk + frow) * 136) + wn + np * 16 + fcol) * 2;
                uint32_t r0, r1, r2, r3;
                LDSM_X4_T(r0, r1, r2, r3, addr);
                b[np * 2 + 0][0] = r0;
                b[np * 2 + 0][1] = r1;
                b[np * 2 + 1][0] = r2;
                b[np * 2 + 1][1] = r3;
            }
#pragma unroll
            for (int mt = 0; mt < 2; mt++)
#pragma unroll
                for (int nt = 0; nt < 8; nt++)
                    mma_f16(acc[mt][nt], a[mt], b[nt][0], b[nt][1]);
        }
        __syncthreads();
    }

    // ---- epilogue: fp16 stores ----
#pragma unroll
    for (int mt = 0; mt < 2; mt++) {
#pragma unroll
        for (int nt = 0; nt < 8; nt++) {
            int r0 = bm + wm + mt * 16 + gid;
            int cc = bn + wn + nt * 8 + 2 * tig;
            if (r0 < M_NODES)
                *reinterpret_cast<__half2*>(&C[(size_t)r0 * N_FOUT + cc]) =
                    __floats2half2_rn(acc[mt][nt][0], acc[mt][nt][1]);
            int r1 = r0 + 8;
            if (r1 < M_NODES)
                *reinterpret_cast<__half2*>(&C[(size_t)r1 * N_FOUT + cc]) =
                    __floats2half2_rn(acc[mt][nt][2], acc[mt][nt][3]);
        }
    }
}

// ---------------------------------------------------------------------------
// CSR construction: count -> scan -> scatter
// ---------------------------------------------------------------------------
__global__ __launch_bounds__(256)
void count_kernel(const int* __restrict__ rows)
{
    int idx = blockIdx.x * blockDim.x + threadIdx.x;
    int stride = gridDim.x * blockDim.x;
    for (int e = idx; e < N_EDGES; e += stride) {
        atomicAdd(&g_row_count[rows[e]], 1);
    }
}

#define SCAN_T 1024
__global__ __launch_bounds__(SCAN_T)
void scan_kernel()
{
    __shared__ int part[SCAN_T];
    const int chunk = (M_NODES + SCAN_T - 1) / SCAN_T;
    int t = threadIdx.x;
    int begin = t * chunk;
    int end   = begin + chunk;
    if (end > M_NODES) end = M_NODES;
    if (begin > M_NODES) begin = M_NODES;

    int s = 0;
    for (int i = begin; i < end; i++) s += g_row_count[i];
    part[t] = s;
    __syncthreads();

    for (int off = 1; off < SCAN_T; off <<= 1) {
        int v = 0;
        if (t >= off) v = part[t - off];
        __syncthreads();
        part[t] += v;
        __syncthreads();
    }

    int run = (t == 0) ? 0 : part[t - 1];
    for (int i = begin; i < end; i++) {
        g_row_start[i] = run;
        run += g_row_count[i];
    }
    if (t == SCAN_T - 1) g_row_start[M_NODES] = run;
}

__global__ __launch_bounds__(256)
void scatter_kernel(const int*   __restrict__ rows,
                    const int*   __restrict__ cols,
                    const float* __restrict__ vals)
{
    int idx = blockIdx.x * blockDim.x + threadIdx.x;
    int stride = gridDim.x * blockDim.x;
    for (int e = idx; e < N_EDGES; e += stride) {
        int r = rows[e];
        int pos = g_row_start[r] + atomicAdd(&g_row_fill[r], 1);
        g_csr_col[pos] = cols[e];
        g_csr_val[pos] = vals[e];
    }
}

// ---------------------------------------------------------------------------
// Kernel 2: CSR SpMM + fused ReLU (one warp per row), fp16 h.
// 4-way unrolled: 4 independent LDG.128 per lane in flight (MLP).
// ---------------------------------------------------------------------------
__global__ __launch_bounds__(256)
void spmm_csr_kernel(const __half* __restrict__ h,
                     float*        __restrict__ out)
{
    int warp_global = (blockIdx.x * blockDim.x + threadIdx.x) >> 5;
    int lane = threadIdx.x & 31;
    if (warp_global >= M_NODES) return;

    int row = warp_global;
    int s = g_row_start[row];
    int e = g_row_start[row + 1];

    float acc[8];
#pragma unroll
    for (int i = 0; i < 8; i++) acc[i] = 0.f;

    int i = s;
    for (; i + 4 <= e; i += 4) {
        int   c0 = g_csr_col[i + 0], c1 = g_csr_col[i + 1];
        int   c2 = g_csr_col[i + 2], c3 = g_csr_col[i + 3];
        float v0 = g_csr_val[i + 0], v1 = g_csr_val[i + 1];
        float v2 = g_csr_val[i + 2], v3 = g_csr_val[i + 3];
        uint4 p0 = __ldg(reinterpret_cast<const uint4*>(h + (size_t)c0 * N_FOUT) + lane);
        uint4 p1 = __ldg(reinterpret_cast<const uint4*>(h + (size_t)c1 * N_FOUT) + lane);
        uint4 p2 = __ldg(reinterpret_cast<const uint4*>(h + (size_t)c2 * N_FOUT) + lane);
        uint4 p3 = __ldg(reinterpret_cast<const uint4*>(h + (size_t)c3 * N_FOUT) + lane);
        const __half2* q0 = reinterpret_cast<const __half2*>(&p0);
        const __half2* q1 = reinterpret_cast<const __half2*>(&p1);
        const __half2* q2 = reinterpret_cast<const __half2*>(&p2);
        const __half2* q3 = reinterpret_cast<const __half2*>(&p3);
#pragma unroll
        for (int j = 0; j < 4; j++) {
            float2 f0 = __half22float2(q0[j]);
            float2 f1 = __half22float2(q1[j]);
            float2 f2 = __half22float2(q2[j]);
            float2 f3 = __half22float2(q3[j]);
            acc[2 * j + 0] += v0 * f0.x + v1 * f1.x + v2 * f2.x + v3 * f3.x;
            acc[2 * j + 1] += v0 * f0.y + v1 * f1.y + v2 * f2.y + v3 * f3.y;
        }
    }
    for (; i < e; i++) {
        int   c = g_csr_col[i];
        float v = g_csr_val[i];
        uint4 p = __ldg(reinterpret_cast<const uint4*>(h + (size_t)c * N_FOUT) + lane);
        const __half2* q = reinterpret_cast<const __half2*>(&p);
#pragma unroll
        for (int j = 0; j < 4; j++) {
            float2 f = __half22float2(q[j]);
            acc[2 * j + 0] += v * f.x;
            acc[2 * j + 1] += v * f.y;
        }
    }

    float* orow = out + (size_t)row * N_FOUT + lane * 8;
    float4 o0 = make_float4(fmaxf(acc[0], 0.f), fmaxf(acc[1], 0.f),
                            fmaxf(acc[2], 0.f), fmaxf(acc[3], 0.f));
    float4 o1 = make_float4(fmaxf(acc[4], 0.f), fmaxf(acc[5], 0.f),
                            fmaxf(acc[6], 0.f), fmaxf(acc[7], 0.f));
    *reinterpret_cast<float4*>(orow + 0) = o0;
    *reinterpret_cast<float4*>(orow + 4) = o1;
}

// ---------------------------------------------------------------------------
// Launch: s1: convert W,x -> fp16 GEMM ; s2 (forked): CSR build ; join ; SpMM
// ---------------------------------------------------------------------------
extern "C" void kernel_launch(void* const* d_in, const int* in_sizes, int n_in,
                              void* d_out, int out_size)
{
    const float* x        = (const float*)d_in[0];
    const int*   adj_rows = (const int*)  d_in[1];
    const int*   adj_cols = (const int*)  d_in[2];
    const float* adj_vals = (const float*)d_in[3];
    const float* weight   = (const float*)d_in[4];
    float*       out      = (float*)d_out;

    __half* xh = nullptr;
    __half* wh = nullptr;
    __half* h  = nullptr;
    int*    row_count = nullptr;
    int*    row_fill  = nullptr;
    cudaGetSymbolAddress((void**)&xh, g_xh);
    cudaGetSymbolAddress((void**)&wh, g_wh);
    cudaGetSymbolAddress((void**)&h,  g_h);
    cudaGetSymbolAddress((void**)&row_count, g_row_count);
    cudaGetSymbolAddress((void**)&row_fill, g_row_fill);

    static cudaStream_t s2 = nullptr;
    static cudaEvent_t ev_fork = nullptr, ev_join = nullptr;
    if (s2 == nullptr) {
        cudaStreamCreateWithFlags(&s2, cudaStreamNonBlocking);
        cudaEventCreateWithFlags(&ev_fork, cudaEventDisableTiming);
        cudaEventCreateWithFlags(&ev_join, cudaEventDisableTiming);
    }

    // ---- fork: branch B (CSR build) onto s2 ----
    cudaEventRecord(ev_fork, 0);
    cudaStreamWaitEvent(s2, ev_fork, 0);

    cudaMemsetAsync(row_count, 0, M_NODES * sizeof(int), s2);
    cudaMemsetAsync(row_fill,  0, M_NODES * sizeof(int), s2);
    count_kernel<<<2048, 256, 0, s2>>>(adj_rows);
    scan_kernel<<<1, SCAN_T, 0, s2>>>();
    scatter_kernel<<<2048, 256, 0, s2>>>(adj_rows, adj_cols, adj_vals);
    cudaEventRecord(ev_join, s2);

    // Branch A on the main stream: convert to fp16, then GEMM
    convert_w_kernel<<<64, 256>>>(weight, wh);
    convert_x_kernel<<<2048, 256>>>(x, xh);
    dim3 ggrid((M_NODES + 127) / 128, N_FOUT / 128);
    hgemm_kernel<<<ggrid, 256>>>(xh, wh, h);

    // ---- join, then SpMM ----
    cudaStreamWaitEvent(0, ev_join, 0);
    int nblocks = (M_NODES * 32 + 255) / 256;
    spmm_csr_kernel<<<nblocks, 256>>>(h, out);
}

// round 14
// speedup vs baseline: 3.0114x; 1.0059x over previous
#include <cuda_runtime.h>
#include <cuda_fp16.h>
#include <cuda_bf16.h>
#include <cstddef>
#include <cstdint>

// Problem constants (fixed by the dataset)
#define M_NODES 100000
#define K_FIN   512
#define N_FOUT  256
#define N_EDGES 3200000

// ---------------------------------------------------------------------------
// Static device scratch (no allocations allowed anywhere)
// ---------------------------------------------------------------------------
__device__ __half g_xh[(size_t)M_NODES * K_FIN];       // x in fp16 (102.4 MB)
__device__ __half g_wh[K_FIN * N_FOUT];                // W in fp16 (0.25 MB)
__device__ __half g_h[(size_t)M_NODES * N_FOUT];       // h = x @ W  (51.2 MB)
__device__ int    g_row_count[M_NODES];
__device__ int    g_row_start[M_NODES + 1];
__device__ int    g_row_fill[M_NODES];
__device__ int2   g_csr_cv[N_EDGES];                   // packed (col, val-bits)

// ---------------------------------------------------------------------------
// fp16 MMA + ldmatrix helpers
// ---------------------------------------------------------------------------
__device__ __forceinline__ void mma_f16(float* c, const uint32_t* a,
                                        uint32_t b0, uint32_t b1) {
    asm volatile(
        "mma.sync.aligned.m16n8k16.row.col.f32.f16.f16.f32 "
        "{%0,%1,%2,%3}, {%4,%5,%6,%7}, {%8,%9}, {%0,%1,%2,%3};\n"
        : "+f"(c[0]), "+f"(c[1]), "+f"(c[2]), "+f"(c[3])
        : "r"(a[0]), "r"(a[1]), "r"(a[2]), "r"(a[3]), "r"(b0), "r"(b1));
}

#define LDSM_X4(r0, r1, r2, r3, addr)                                        \
    asm volatile("ldmatrix.sync.aligned.m8n8.x4.shared.b16 {%0,%1,%2,%3},[%4];" \
                 : "=r"(r0), "=r"(r1), "=r"(r2), "=r"(r3) : "r"(addr))

#define LDSM_X4_T(r0, r1, r2, r3, addr)                                      \
    asm volatile("ldmatrix.sync.aligned.m8n8.x4.trans.shared.b16 {%0,%1,%2,%3},[%4];" \
                 : "=r"(r0), "=r"(r1), "=r"(r2), "=r"(r3) : "r"(addr))

// ---------------------------------------------------------------------------
// Conversion kernels: f32 -> f16
// ---------------------------------------------------------------------------
__global__ __launch_bounds__(256)
void convert_x_kernel(const float* __restrict__ in, __half* __restrict__ out)
{
    const size_t total4 = (size_t)M_NODES * K_FIN / 4;
    size_t idx = (size_t)blockIdx.x * blockDim.x + threadIdx.x;
    size_t stride = (size_t)gridDim.x * blockDim.x;
    __half2* out2 = reinterpret_cast<__half2*>(out);
    for (size_t i = idx; i < total4; i += stride) {
        float4 v = reinterpret_cast<const float4*>(in)[i];
        out2[2 * i + 0] = __floats2half2_rn(v.x, v.y);
        out2[2 * i + 1] = __floats2half2_rn(v.z, v.w);
    }
}

__global__ __launch_bounds__(256)
void convert_w_kernel(const float* __restrict__ in, __half* __restrict__ out)
{
    const int total4 = K_FIN * N_FOUT / 4;
    int idx = blockIdx.x * blockDim.x + threadIdx.x;
    int stride = gridDim.x * blockDim.x;
    __half2* out2 = reinterpret_cast<__half2*>(out);
    for (int i = idx; i < total4; i += stride) {
        float4 v = reinterpret_cast<const float4*>(in)[i];
        out2[2 * i + 0] = __floats2half2_rn(v.x, v.y);
        out2[2 * i + 1] = __floats2half2_rn(v.z, v.w);
    }
}

// ---------------------------------------------------------------------------
// Kernel 1: fp16 HMMA GEMM  h[M,256] = xh[M,512] @ wh[512,256]  (fp32 accum)
// BM=128, BN=128, BK=64; 256 threads = 8 warps (4 m x 2 n), warp tile 32x64.
// ---------------------------------------------------------------------------
__global__ __launch_bounds__(256, 2)
void hgemm_kernel(const __half* __restrict__ A,   // [M, 512] f16
                  const __half* __restrict__ W,   // [512, 256] f16
                  __half* __restrict__ C)         // [M, 256] f16
{
    __shared__ __align__(16) __half As[128][72];    // 18.0 KB
    __shared__ __align__(16) __half Bs[64][136];    // 17.0 KB

    const int tid  = threadIdx.x;
    const int lane = tid & 31;
    const int warp = tid >> 5;
    const int gid  = lane >> 2;
    const int tig  = lane & 3;
    const int wm   = (warp & 3) * 32;
    const int wn   = (warp >> 2) * 64;
    const int bm   = blockIdx.x * 128;
    const int bn   = blockIdx.y * 128;

    const int li   = lane >> 3;
    const int l7   = lane & 7;
    const int frow = ((li & 1) << 3) + l7;
    const int fcol = (li >> 1) << 3;

    const uint32_t as_base = (uint32_t)__cvta_generic_to_shared(&As[0][0]);
    const uint32_t bs_base = (uint32_t)__cvta_generic_to_shared(&Bs[0][0]);

    const int a_row = tid >> 2;
    const int a_h0  = (tid & 3) << 4;
    const int b_kr  = tid >> 3;
    const int b_h0  = (tid & 7) << 4;

    float acc[2][8][4];
#pragma unroll
    for (int mt = 0; mt < 2; mt++)
#pragma unroll
        for (int nt = 0; nt < 8; nt++)
#pragma unroll
            for (int i = 0; i < 4; i++) acc[mt][nt][i] = 0.f;

    for (int k0 = 0; k0 < K_FIN; k0 += 64) {
#pragma unroll
        for (int i = 0; i < 2; i++) {
            int row = a_row + i * 64;
            int gm  = bm + row;
            uint4 v0, v1;
            if (gm < M_NODES) {
                const __half* ap = A + (size_t)gm * K_FIN + k0 + a_h0;
                v0 = *reinterpret_cast<const uint4*>(ap);
                v1 = *reinterpret_cast<const uint4*>(ap + 8);
            } else {
                v0 = make_uint4(0, 0, 0, 0);
                v1 = make_uint4(0, 0, 0, 0);
            }
            *reinterpret_cast<uint4*>(&As[row][a_h0 + 0]) = v0;
            *reinterpret_cast<uint4*>(&As[row][a_h0 + 8]) = v1;
        }
#pragma unroll
        for (int i = 0; i < 2; i++) {
            int kr = b_kr + i * 32;
            const __half* bp = W + (size_t)(k0 + kr) * N_FOUT + bn + b_h0;
            uint4 v0 = *reinterpret_cast<const uint4*>(bp);
            uint4 v1 = *reinterpret_cast<const uint4*>(bp + 8);
            *reinterpret_cast<uint4*>(&Bs[kr][b_h0 + 0]) = v0;
            *reinterpret_cast<uint4*>(&Bs[kr][b_h0 + 8]) = v1;
        }
        __syncthreads();

#pragma unroll
        for (int ks = 0; ks < 4; ks++) {
            const int kk = ks * 16;
            uint32_t a[2][4];
#pragma unroll
            for (int mt = 0; mt < 2; mt++) {
                uint32_t addr = as_base +
                    (((wm + mt * 16 + frow) * 72) + kk + fcol) * 2;
                LDSM_X4(a[mt][0], a[mt][1], a[mt][2], a[mt][3], addr);
            }
            uint32_t b[8][2];
#pragma unroll
            for (int np = 0; np < 4; np++) {
                uint32_t addr = bs_base +
                    (((kk + frow) * 136) + wn + np * 16 + fcol) * 2;
                uint32_t r0, r1, r2, r3;
                LDSM_X4_T(r0, r1, r2, r3, addr);
                b[np * 2 + 0][0] = r0;
                b[np * 2 + 0][1] = r1;
                b[np * 2 + 1][0] = r2;
                b[np * 2 + 1][1] = r3;
            }
#pragma unroll
            for (int mt = 0; mt < 2; mt++)
#pragma unroll
                for (int nt = 0; nt < 8; nt++)
                    mma_f16(acc[mt][nt], a[mt], b[nt][0], b[nt][1]);
        }
        __syncthreads();
    }

#pragma unroll
    for (int mt = 0; mt < 2; mt++) {
#pragma unroll
        for (int nt = 0; nt < 8; nt++) {
            int r0 = bm + wm + mt * 16 + gid;
            int cc = bn + wn + nt * 8 + 2 * tig;
            if (r0 < M_NODES)
                *reinterpret_cast<__half2*>(&C[(size_t)r0 * N_FOUT + cc]) =
                    __floats2half2_rn(acc[mt][nt][0], acc[mt][nt][1]);
            int r1 = r0 + 8;
            if (r1 < M_NODES)
                *reinterpret_cast<__half2*>(&C[(size_t)r1 * N_FOUT + cc]) =
                    __floats2half2_rn(acc[mt][nt][2], acc[mt][nt][3]);
        }
    }
}

// ---------------------------------------------------------------------------
// CSR construction: count -> scan -> scatter (packed int2 payload)
// ---------------------------------------------------------------------------
__global__ __launch_bounds__(256)
void count_kernel(const int* __restrict__ rows)
{
    int idx = blockIdx.x * blockDim.x + threadIdx.x;
    int stride = gridDim.x * blockDim.x;
    for (int e = idx; e < N_EDGES; e += stride) {
        atomicAdd(&g_row_count[rows[e]], 1);
    }
}

#define SCAN_T 1024
__global__ __launch_bounds__(SCAN_T)
void scan_kernel()
{
    __shared__ int part[SCAN_T];
    const int chunk = (M_NODES + SCAN_T - 1) / SCAN_T;
    int t = threadIdx.x;
    int begin = t * chunk;
    int end   = begin + chunk;
    if (end > M_NODES) end = M_NODES;
    if (begin > M_NODES) begin = M_NODES;

    int s = 0;
    for (int i = begin; i < end; i++) s += g_row_count[i];
    part[t] = s;
    __syncthreads();

    for (int off = 1; off < SCAN_T; off <<= 1) {
        int v = 0;
        if (t >= off) v = part[t - off];
        __syncthreads();
        part[t] += v;
        __syncthreads();
    }

    int run = (t == 0) ? 0 : part[t - 1];
    for (int i = begin; i < end; i++) {
        g_row_start[i] = run;
        run += g_row_count[i];
    }
    if (t == SCAN_T - 1) g_row_start[M_NODES] = run;
}

__global__ __launch_bounds__(256)
void scatter_kernel(const int*   __restrict__ rows,
                    const int*   __restrict__ cols,
                    const float* __restrict__ vals)
{
    int idx = blockIdx.x * blockDim.x + threadIdx.x;
    int stride = gridDim.x * blockDim.x;
    for (int e = idx; e < N_EDGES; e += stride) {
        int r = rows[e];
        int pos = g_row_start[r] + atomicAdd(&g_row_fill[r], 1);
        g_csr_cv[pos] = make_int2(cols[e], __float_as_int(vals[e]));
    }
}

// ---------------------------------------------------------------------------
// Kernel 2: CSR SpMM + fused ReLU (one warp per row), fp16 h, packed edges.
// ---------------------------------------------------------------------------
__global__ __launch_bounds__(256)
void spmm_csr_kernel(const __half* __restrict__ h,
                     float*        __restrict__ out)
{
    int warp_global = (blockIdx.x * blockDim.x + threadIdx.x) >> 5;
    int lane = threadIdx.x & 31;
    if (warp_global >= M_NODES) return;

    int row = warp_global;
    int s = g_row_start[row];
    int e = g_row_start[row + 1];

    float acc[8];
#pragma unroll
    for (int i = 0; i < 8; i++) acc[i] = 0.f;

    int i = s;
    for (; i + 4 <= e; i += 4) {
        int2 cv0 = g_csr_cv[i + 0];
        int2 cv1 = g_csr_cv[i + 1];
        int2 cv2 = g_csr_cv[i + 2];
        int2 cv3 = g_csr_cv[i + 3];
        float v0 = __int_as_float(cv0.y), v1 = __int_as_float(cv1.y);
        float v2 = __int_as_float(cv2.y), v3 = __int_as_float(cv3.y);
        uint4 p0 = __ldg(reinterpret_cast<const uint4*>(h + (size_t)cv0.x * N_FOUT) + lane);
        uint4 p1 = __ldg(reinterpret_cast<const uint4*>(h + (size_t)cv1.x * N_FOUT) + lane);
        uint4 p2 = __ldg(reinterpret_cast<const uint4*>(h + (size_t)cv2.x * N_FOUT) + lane);
        uint4 p3 = __ldg(reinterpret_cast<const uint4*>(h + (size_t)cv3.x * N_FOUT) + lane);
        const __half2* q0 = reinterpret_cast<const __half2*>(&p0);
        const __half2* q1 = reinterpret_cast<const __half2*>(&p1);
        const __half2* q2 = reinterpret_cast<const __half2*>(&p2);
        const __half2* q3 = reinterpret_cast<const __half2*>(&p3);
#pragma unroll
        for (int j = 0; j < 4; j++) {
            float2 f0 = __half22float2(q0[j]);
            float2 f1 = __half22float2(q1[j]);
            float2 f2 = __half22float2(q2[j]);
            float2 f3 = __half22float2(q3[j]);
            acc[2 * j + 0] += v0 * f0.x + v1 * f1.x + v2 * f2.x + v3 * f3.x;
            acc[2 * j + 1] += v0 * f0.y + v1 * f1.y + v2 * f2.y + v3 * f3.y;
        }
    }
    for (; i < e; i++) {
        int2 cv = g_csr_cv[i];
        float v = __int_as_float(cv.y);
        uint4 p = __ldg(reinterpret_cast<const uint4*>(h + (size_t)cv.x * N_FOUT) + lane);
        const __half2* q = reinterpret_cast<const __half2*>(&p);
#pragma unroll
        for (int j = 0; j < 4; j++) {
            float2 f = __half22float2(q[j]);
            acc[2 * j + 0] += v * f.x;
            acc[2 * j + 1] += v * f.y;
        }
    }

    float* orow = out + (size_t)row * N_FOUT + lane * 8;
    float4 o0 = make_float4(fmaxf(acc[0], 0.f), fmaxf(acc[1], 0.f),
                            fmaxf(acc[2], 0.f), fmaxf(acc[3], 0.f));
    float4 o1 = make_float4(fmaxf(acc[4], 0.f), fmaxf(acc[5], 0.f),
                            fmaxf(acc[6], 0.f), fmaxf(acc[7], 0.f));
    *reinterpret_cast<float4*>(orow + 0) = o0;
    *reinterpret_cast<float4*>(orow + 4) = o1;
}

// ---------------------------------------------------------------------------
// Launch: s1: convert_x -> GEMM ; s2 (forked): convert_w + CSR build ;
// join ; SpMM.  (convert_w is independent of branch A's critical path.)
// ---------------------------------------------------------------------------
extern "C" void kernel_launch(void* const* d_in, const int* in_sizes, int n_in,
                              void* d_out, int out_size)
{
    const float* x        = (const float*)d_in[0];
    const int*   adj_rows = (const int*)  d_in[1];
    const int*   adj_cols = (const int*)  d_in[2];
    const float* adj_vals = (const float*)d_in[3];
    const float* weight   = (const float*)d_in[4];
    float*       out      = (float*)d_out;

    __half* xh = nullptr;
    __half* wh = nullptr;
    __half* h  = nullptr;
    int*    row_count = nullptr;
    int*    row_fill  = nullptr;
    cudaGetSymbolAddress((void**)&xh, g_xh);
    cudaGetSymbolAddress((void**)&wh, g_wh);
    cudaGetSymbolAddress((void**)&h,  g_h);
    cudaGetSymbolAddress((void**)&row_count, g_row_count);
    cudaGetSymbolAddress((void**)&row_fill, g_row_fill);

    static cudaStream_t s2 = nullptr;
    static cudaEvent_t ev_fork = nullptr, ev_join = nullptr, ev_w = nullptr;
    if (s2 == nullptr) {
        cudaStreamCreateWithFlags(&s2, cudaStreamNonBlocking);
        cudaEventCreateWithFlags(&ev_fork, cudaEventDisableTiming);
        cudaEventCreateWithFlags(&ev_join, cudaEventDisableTiming);
        cudaEventCreateWithFlags(&ev_w, cudaEventDisableTiming);
    }

    // ---- fork: branch B onto s2 ----
    cudaEventRecord(ev_fork, 0);
    cudaStreamWaitEvent(s2, ev_fork, 0);

    // Branch B on s2: convert_w (tiny, needed before GEMM) then CSR build
    convert_w_kernel<<<64, 256, 0, s2>>>(weight, wh);
    cudaEventRecord(ev_w, s2);
    cudaMemsetAsync(row_count, 0, M_NODES * sizeof(int), s2);
    cudaMemsetAsync(row_fill,  0, M_NODES * sizeof(int), s2);
    count_kernel<<<2048, 256, 0, s2>>>(adj_rows);
    scan_kernel<<<1, SCAN_T, 0, s2>>>();
    scatter_kernel<<<2048, 256, 0, s2>>>(adj_rows, adj_cols, adj_vals);
    cudaEventRecord(ev_join, s2);

    // Branch A on the main stream: convert_x, wait for wh, GEMM
    convert_x_kernel<<<2048, 256>>>(x, xh);
    cudaStreamWaitEvent(0, ev_w, 0);
    dim3 ggrid((M_NODES + 127) / 128, N_FOUT / 128);
    hgemm_kernel<<<ggrid, 256>>>(xh, wh, h);

    // ---- join, then SpMM ----
    cudaStreamWaitEvent(0, ev_join, 0);
    int nblocks = (M_NODES * 32 + 255) / 256;
    spmm_csr_kernel<<<nblocks, 256>>>(h, out);
}

// round 15
// speedup vs baseline: 3.0538x; 1.0141x over previous
#include <cuda_runtime.h>
#include <cuda_fp16.h>
#include <cuda_bf16.h>
#include <cstddef>
#include <cstdint>

// Problem constants (fixed by the dataset)
#define M_NODES 100000
#define K_FIN   512
#define N_FOUT  256
#define N_EDGES 3200000

// GEMM m-chunking for convert/GEMM pipelining
#define MBLOCKS_TOTAL 782          // ceil(100000/128)
#define MBLOCKS_C0    391
#define ROWS_C0       (MBLOCKS_C0 * 128)   // 50048

// ---------------------------------------------------------------------------
// Static device scratch (no allocations allowed anywhere)
// ---------------------------------------------------------------------------
__device__ __half g_xh[(size_t)M_NODES * K_FIN];       // x in fp16 (102.4 MB)
__device__ __half g_wh[K_FIN * N_FOUT];                // W in fp16 (0.25 MB)
__device__ __half g_h[(size_t)M_NODES * N_FOUT];       // h = x @ W  (51.2 MB)
__device__ int    g_row_count[M_NODES];
__device__ int    g_row_start[M_NODES + 1];
__device__ int    g_row_fill[M_NODES];
__device__ int2   g_csr_cv[N_EDGES];                   // packed (col, val-bits)

// ---------------------------------------------------------------------------
// fp16 MMA + ldmatrix + cp.async helpers
// ---------------------------------------------------------------------------
__device__ __forceinline__ void mma_f16(float* c, const uint32_t* a,
                                        uint32_t b0, uint32_t b1) {
    asm volatile(
        "mma.sync.aligned.m16n8k16.row.col.f32.f16.f16.f32 "
        "{%0,%1,%2,%3}, {%4,%5,%6,%7}, {%8,%9}, {%0,%1,%2,%3};\n"
        : "+f"(c[0]), "+f"(c[1]), "+f"(c[2]), "+f"(c[3])
        : "r"(a[0]), "r"(a[1]), "r"(a[2]), "r"(a[3]), "r"(b0), "r"(b1));
}

#define LDSM_X4(r0, r1, r2, r3, addr)                                        \
    asm volatile("ldmatrix.sync.aligned.m8n8.x4.shared.b16 {%0,%1,%2,%3},[%4];" \
                 : "=r"(r0), "=r"(r1), "=r"(r2), "=r"(r3) : "r"(addr))

#define LDSM_X4_T(r0, r1, r2, r3, addr)                                      \
    asm volatile("ldmatrix.sync.aligned.m8n8.x4.trans.shared.b16 {%0,%1,%2,%3},[%4];" \
                 : "=r"(r0), "=r"(r1), "=r"(r2), "=r"(r3) : "r"(addr))

__device__ __forceinline__ void cp_async16(uint32_t dst_smem, const void* src) {
    asm volatile("cp.async.cg.shared.global [%0], [%1], 16;"
                 :: "r"(dst_smem), "l"(src));
}
#define CP_COMMIT()  asm volatile("cp.async.commit_group;")
#define CP_WAIT(n)   asm volatile("cp.async.wait_group %0;" :: "n"(n))

// ---------------------------------------------------------------------------
// Conversion kernels: f32 -> f16
// ---------------------------------------------------------------------------
__global__ __launch_bounds__(256)
void convert_x_chunk_kernel(const float* __restrict__ in, __half* __restrict__ out,
                            size_t elem4_off, size_t n_elem4)
{
    size_t idx = (size_t)blockIdx.x * blockDim.x + threadIdx.x;
    size_t stride = (size_t)gridDim.x * blockDim.x;
    __half2* out2 = reinterpret_cast<__half2*>(out);
    for (size_t i = idx; i < n_elem4; i += stride) {
        size_t g = elem4_off + i;
        float4 v = reinterpret_cast<const float4*>(in)[g];
        out2[2 * g + 0] = __floats2half2_rn(v.x, v.y);
        out2[2 * g + 1] = __floats2half2_rn(v.z, v.w);
    }
}

__global__ __launch_bounds__(256)
void convert_w_kernel(const float* __restrict__ in, __half* __restrict__ out)
{
    const int total4 = K_FIN * N_FOUT / 4;
    int idx = blockIdx.x * blockDim.x + threadIdx.x;
    int stride = gridDim.x * blockDim.x;
    __half2* out2 = reinterpret_cast<__half2*>(out);
    for (int i = idx; i < total4; i += stride) {
        float4 v = reinterpret_cast<const float4*>(in)[i];
        out2[2 * i + 0] = __floats2half2_rn(v.x, v.y);
        out2[2 * i + 1] = __floats2half2_rn(v.z, v.w);
    }
}

// ---------------------------------------------------------------------------
// Kernel 1: fp16 HMMA GEMM with cp.async double-buffered smem pipeline.
// BM=128, BN=128, BK=64; 256 threads = 8 warps (4 m x 2 n), warp tile 32x64.
// Dynamic smem: 2 stages x (As 128x72 + Bs 64x136) halves = 70 KB.
// ---------------------------------------------------------------------------
#define AS_HALVES (128 * 72)
#define BS_HALVES (64 * 136)
#define SMEM_BYTES ((2 * AS_HALVES + 2 * BS_HALVES) * 2)

__global__ __launch_bounds__(256, 2)
void hgemm_kernel(const __half* __restrict__ A,   // [M, 512] f16
                  const __half* __restrict__ W,   // [512, 256] f16
                  __half* __restrict__ C,         // [M, 256] f16
                  int m_off)                      // m-block offset
{
    extern __shared__ __half smem[];
    __half* As0 = smem;                       // [128][72]
    __half* As1 = As0 + AS_HALVES;
    __half* Bs0 = As1 + AS_HALVES;            // [64][136]
    __half* Bs1 = Bs0 + BS_HALVES;

    const int tid  = threadIdx.x;
    const int lane = tid & 31;
    const int warp = tid >> 5;
    const int gid  = lane >> 2;
    const int tig  = lane & 3;
    const int wm   = (warp & 3) * 32;
    const int wn   = (warp >> 2) * 64;
    const int bm   = (blockIdx.x + m_off) * 128;
    const int bn   = blockIdx.y * 128;

    const int li   = lane >> 3;
    const int l7   = lane & 7;
    const int frow = ((li & 1) << 3) + l7;
    const int fcol = (li >> 1) << 3;

    const uint32_t as_base[2] = {
        (uint32_t)__cvta_generic_to_shared(As0),
        (uint32_t)__cvta_generic_to_shared(As1) };
    const uint32_t bs_base[2] = {
        (uint32_t)__cvta_generic_to_shared(Bs0),
        (uint32_t)__cvta_generic_to_shared(Bs1) };

    // Staging map: A thread -> rows {tid>>2, +64}, 16-half chunk (tid&3)*16
    //              B thread -> k-rows {tid>>3, +32}, 16-half chunk (tid&7)*16
    const int a_row = tid >> 2;
    const int a_h0  = (tid & 3) << 4;
    const int b_kr  = tid >> 3;
    const int b_h0  = (tid & 7) << 4;

    // Clamped A row indices (out-of-range rows compute garbage; never stored)
    int gma0 = bm + a_row;       if (gma0 >= M_NODES) gma0 = 0;
    int gma1 = bm + a_row + 64;  if (gma1 >= M_NODES) gma1 = 0;

    // stage(buf, k0): issue cp.asyncs for one k-tile
    auto stage = [&](int buf, int k0) {
        const __half* ap0 = A + (size_t)gma0 * K_FIN + k0 + a_h0;
        const __half* ap1 = A + (size_t)gma1 * K_FIN + k0 + a_h0;
        uint32_t d0 = as_base[buf] + ((a_row)      * 72 + a_h0) * 2;
        uint32_t d1 = as_base[buf] + ((a_row + 64) * 72 + a_h0) * 2;
        cp_async16(d0,      ap0);
        cp_async16(d0 + 16, ap0 + 8);
        cp_async16(d1,      ap1);
        cp_async16(d1 + 16, ap1 + 8);
        const __half* bp0 = W + (size_t)(k0 + b_kr)      * N_FOUT + bn + b_h0;
        const __half* bp1 = W + (size_t)(k0 + b_kr + 32) * N_FOUT + bn + b_h0;
        uint32_t e0 = bs_base[buf] + ((b_kr)      * 136 + b_h0) * 2;
        uint32_t e1 = bs_base[buf] + ((b_kr + 32) * 136 + b_h0) * 2;
        cp_async16(e0,      bp0);
        cp_async16(e0 + 16, bp0 + 8);
        cp_async16(e1,      bp1);
        cp_async16(e1 + 16, bp1 + 8);
    };

    float acc[2][8][4];
#pragma unroll
    for (int mt = 0; mt < 2; mt++)
#pragma unroll
        for (int nt = 0; nt < 8; nt++)
#pragma unroll
            for (int i = 0; i < 4; i++) acc[mt][nt][i] = 0.f;

    stage(0, 0);
    CP_COMMIT();

    const int NTILES = K_FIN / 64;   // 8
#pragma unroll 1
    for (int kt = 0; kt < NTILES; kt++) {
        const int buf = kt & 1;
        if (kt + 1 < NTILES) {
            stage(buf ^ 1, (kt + 1) * 64);
            CP_COMMIT();
            CP_WAIT(1);          // tile kt's group complete
        } else {
            CP_WAIT(0);
        }
        __syncthreads();

#pragma unroll
        for (int ks = 0; ks < 4; ks++) {
            const int kk = ks * 16;
            uint32_t a[2][4];
#pragma unroll
            for (int mt = 0; mt < 2; mt++) {
                uint32_t addr = as_base[buf] +
                    (((wm + mt * 16 + frow) * 72) + kk + fcol) * 2;
                LDSM_X4(a[mt][0], a[mt][1], a[mt][2], a[mt][3], addr);
            }
            uint32_t b[8][2];
#pragma unroll
            for (int np = 0; np < 4; np++) {
                uint32_t addr = bs_base[buf] +
                    (((kk + frow) * 136) + wn + np * 16 + fcol) * 2;
                uint32_t r0, r1, r2, r3;
                LDSM_X4_T(r0, r1, r2, r3, addr);
                b[np * 2 + 0][0] = r0;
                b[np * 2 + 0][1] = r1;
                b[np * 2 + 1][0] = r2;
                b[np * 2 + 1][1] = r3;
            }
#pragma unroll
            for (int mt = 0; mt < 2; mt++)
#pragma unroll
                for (int nt = 0; nt < 8; nt++)
                    mma_f16(acc[mt][nt], a[mt], b[nt][0], b[nt][1]);
        }
        __syncthreads();   // compute done before next stage overwrites buf
    }

    // ---- epilogue: fp16 stores ----
#pragma unroll
    for (int mt = 0; mt < 2; mt++) {
#pragma unroll
        for (int nt = 0; nt < 8; nt++) {
            int r0 = bm + wm + mt * 16 + gid;
            int cc = bn + wn + nt * 8 + 2 * tig;
            if (r0 < M_NODES)
                *reinterpret_cast<__half2*>(&C[(size_t)r0 * N_FOUT + cc]) =
                    __floats2half2_rn(acc[mt][nt][0], acc[mt][nt][1]);
            int r1 = r0 + 8;
            if (r1 < M_NODES)
                *reinterpret_cast<__half2*>(&C[(size_t)r1 * N_FOUT + cc]) =
                    __floats2half2_rn(acc[mt][nt][2], acc[mt][nt][3]);
        }
    }
}

// ---------------------------------------------------------------------------
// CSR construction: count -> scan -> scatter (packed int2 payload)
// ---------------------------------------------------------------------------
__global__ __launch_bounds__(256)
void count_kernel(const int* __restrict__ rows)
{
    int idx = blockIdx.x * blockDim.x + threadIdx.x;
    int stride = gridDim.x * blockDim.x;
    for (int e = idx; e < N_EDGES; e += stride) {
        atomicAdd(&g_row_count[rows[e]], 1);
    }
}

#define SCAN_T 1024
__global__ __launch_bounds__(SCAN_T)
void scan_kernel()
{
    __shared__ int part[SCAN_T];
    const int chunk = (M_NODES + SCAN_T - 1) / SCAN_T;
    int t = threadIdx.x;
    int begin = t * chunk;
    int end   = begin + chunk;
    if (end > M_NODES) end = M_NODES;
    if (begin > M_NODES) begin = M_NODES;

    int s = 0;
    for (int i = begin; i < end; i++) s += g_row_count[i];
    part[t] = s;
    __syncthreads();

    for (int off = 1; off < SCAN_T; off <<= 1) {
        int v = 0;
        if (t >= off) v = part[t - off];
        __syncthreads();
        part[t] += v;
        __syncthreads();
    }

    int run = (t == 0) ? 0 : part[t - 1];
    for (int i = begin; i < end; i++) {
        g_row_start[i] = run;
        run += g_row_count[i];
    }
    if (t == SCAN_T - 1) g_row_start[M_NODES] = run;
}

__global__ __launch_bounds__(256)
void scatter_kernel(const int*   __restrict__ rows,
                    const int*   __restrict__ cols,
                    const float* __restrict__ vals)
{
    int idx = blockIdx.x * blockDim.x + threadIdx.x;
    int stride = gridDim.x * blockDim.x;
    for (int e = idx; e < N_EDGES; e += stride) {
        int r = rows[e];
        int pos = g_row_start[r] + atomicAdd(&g_row_fill[r], 1);
        g_csr_cv[pos] = make_int2(cols[e], __float_as_int(vals[e]));
    }
}

// ---------------------------------------------------------------------------
// Kernel 2: CSR SpMM + fused ReLU (one warp per row), fp16 h, packed edges.
// ---------------------------------------------------------------------------
__global__ __launch_bounds__(256)
void spmm_csr_kernel(const __half* __restrict__ h,
                     float*        __restrict__ out)
{
    int warp_global = (blockIdx.x * blockDim.x + threadIdx.x) >> 5;
    int lane = threadIdx.x & 31;
    if (warp_global >= M_NODES) return;

    int row = warp_global;
    int s = g_row_start[row];
    int e = g_row_start[row + 1];

    float acc[8];
#pragma unroll
    for (int i = 0; i < 8; i++) acc[i] = 0.f;

    int i = s;
    for (; i + 4 <= e; i += 4) {
        int2 cv0 = g_csr_cv[i + 0];
        int2 cv1 = g_csr_cv[i + 1];
        int2 cv2 = g_csr_cv[i + 2];
        int2 cv3 = g_csr_cv[i + 3];
        float v0 = __int_as_float(cv0.y), v1 = __int_as_float(cv1.y);
        float v2 = __int_as_float(cv2.y), v3 = __int_as_float(cv3.y);
        uint4 p0 = __ldg(reinterpret_cast<const uint4*>(h + (size_t)cv0.x * N_FOUT) + lane);
        uint4 p1 = __ldg(reinterpret_cast<const uint4*>(h + (size_t)cv1.x * N_FOUT) + lane);
        uint4 p2 = __ldg(reinterpret_cast<const uint4*>(h + (size_t)cv2.x * N_FOUT) + lane);
        uint4 p3 = __ldg(reinterpret_cast<const uint4*>(h + (size_t)cv3.x * N_FOUT) + lane);
        const __half2* q0 = reinterpret_cast<const __half2*>(&p0);
        const __half2* q1 = reinterpret_cast<const __half2*>(&p1);
        const __half2* q2 = reinterpret_cast<const __half2*>(&p2);
        const __half2* q3 = reinterpret_cast<const __half2*>(&p3);
#pragma unroll
        for (int j = 0; j < 4; j++) {
            float2 f0 = __half22float2(q0[j]);
            float2 f1 = __half22float2(q1[j]);
            float2 f2 = __half22float2(q2[j]);
            float2 f3 = __half22float2(q3[j]);
            acc[2 * j + 0] += v0 * f0.x + v1 * f1.x + v2 * f2.x + v3 * f3.x;
            acc[2 * j + 1] += v0 * f0.y + v1 * f1.y + v2 * f2.y + v3 * f3.y;
        }
    }
    for (; i < e; i++) {
        int2 cv = g_csr_cv[i];
        float v = __int_as_float(cv.y);
        uint4 p = __ldg(reinterpret_cast<const uint4*>(h + (size_t)cv.x * N_FOUT) + lane);
        const __half2* q = reinterpret_cast<const __half2*>(&p);
#pragma unroll
        for (int j = 0; j < 4; j++) {
            float2 f = __half22float2(q[j]);
            acc[2 * j + 0] += v * f.x;
            acc[2 * j + 1] += v * f.y;
        }
    }

    float* orow = out + (size_t)row * N_FOUT + lane * 8;
    float4 o0 = make_float4(fmaxf(acc[0], 0.f), fmaxf(acc[1], 0.f),
                            fmaxf(acc[2], 0.f), fmaxf(acc[3], 0.f));
    float4 o1 = make_float4(fmaxf(acc[4], 0.f), fmaxf(acc[5], 0.f),
                            fmaxf(acc[6], 0.f), fmaxf(acc[7], 0.f));
    *reinterpret_cast<float4*>(orow + 0) = o0;
    *reinterpret_cast<float4*>(orow + 4) = o1;
}

// ---------------------------------------------------------------------------
// Launch:
//  s1: convert_x(chunk0) -> GEMM(chunk0) -> GEMM(chunk1) -> SpMM
//  s2: convert_w + CSR build (forked)
//  s3: convert_x(chunk1)  (forked; GEMM(chunk1) waits on it)
// ---------------------------------------------------------------------------
extern "C" void kernel_launch(void* const* d_in, const int* in_sizes, int n_in,
                              void* d_out, int out_size)
{
    const float* x        = (const float*)d_in[0];
    const int*   adj_rows = (const int*)  d_in[1];
    const int*   adj_cols = (const int*)  d_in[2];
    const float* adj_vals = (const float*)d_in[3];
    const float* weight   = (const float*)d_in[4];
    float*       out      = (float*)d_out;

    __half* xh = nullptr;
    __half* wh = nullptr;
    __half* h  = nullptr;
    int*    row_count = nullptr;
    int*    row_fill  = nullptr;
    cudaGetSymbolAddress((void**)&xh, g_xh);
    cudaGetSymbolAddress((void**)&wh, g_wh);
    cudaGetSymbolAddress((void**)&h,  g_h);
    cudaGetSymbolAddress((void**)&row_count, g_row_count);
    cudaGetSymbolAddress((void**)&row_fill, g_row_fill);

    static cudaStream_t s2 = nullptr, s3 = nullptr;
    static cudaEvent_t ev_fork = nullptr, ev_join = nullptr, ev_w = nullptr, ev_c2 = nullptr;
    if (s2 == nullptr) {
        cudaStreamCreateWithFlags(&s2, cudaStreamNonBlocking);
        cudaStreamCreateWithFlags(&s3, cudaStreamNonBlocking);
        cudaEventCreateWithFlags(&ev_fork, cudaEventDisableTiming);
        cudaEventCreateWithFlags(&ev_join, cudaEventDisableTiming);
        cudaEventCreateWithFlags(&ev_w, cudaEventDisableTiming);
        cudaEventCreateWithFlags(&ev_c2, cudaEventDisableTiming);
        cudaFuncSetAttribute(hgemm_kernel,
                             cudaFuncAttributeMaxDynamicSharedMemorySize,
                             SMEM_BYTES);
    }

    // ---- fork ----
    cudaEventRecord(ev_fork, 0);
    cudaStreamWaitEvent(s2, ev_fork, 0);
    cudaStreamWaitEvent(s3, ev_fork, 0);

    // Branch B on s2: convert_w then CSR build
    convert_w_kernel<<<64, 256, 0, s2>>>(weight, wh);
    cudaEventRecord(ev_w, s2);
    cudaMemsetAsync(row_count, 0, M_NODES * sizeof(int), s2);
    cudaMemsetAsync(row_fill,  0, M_NODES * sizeof(int), s2);
    count_kernel<<<2048, 256, 0, s2>>>(adj_rows);
    scan_kernel<<<1, SCAN_T, 0, s2>>>();
    scatter_kernel<<<2048, 256, 0, s2>>>(adj_rows, adj_cols, adj_vals);
    cudaEventRecord(ev_join, s2);

    // Branch C on s3: convert x chunk1
    const size_t e4_c0 = (size_t)ROWS_C0 * K_FIN / 4;
    const size_t e4_total = (size_t)M_NODES * K_FIN / 4;
    convert_x_chunk_kernel<<<1024, 256, 0, s3>>>(x, xh, e4_c0, e4_total - e4_c0);
    cudaEventRecord(ev_c2, s3);

    // Branch A on s1: convert x chunk0, GEMM chunk0, GEMM chunk1
    convert_x_chunk_kernel<<<1024, 256>>>(x, xh, 0, e4_c0);
    cudaStreamWaitEvent(0, ev_w, 0);
    dim3 g0(MBLOCKS_C0, N_FOUT / 128);
    hgemm_kernel<<<g0, 256, SMEM_BYTES>>>(xh, wh, h, 0);
    cudaStreamWaitEvent(0, ev_c2, 0);
    dim3 g1(MBLOCKS_TOTAL - MBLOCKS_C0, N_FOUT / 128);
    hgemm_kernel<<<g1, 256, SMEM_BYTES>>>(xh, wh, h, MBLOCKS_C0);

    // ---- join, then SpMM ----
    cudaStreamWaitEvent(0, ev_join, 0);
    int nblocks = (M_NODES * 32 + 255) / 256;
    spmm_csr_kernel<<<nblocks, 256>>>(h, out);
}